// round 1
// baseline (speedup 1.0000x reference)
#include <cuda_runtime.h>
#include <math.h>

#define BB 8
#define CC 512
#define LL 2048

// Scratch: q,k,v [B,C,L] and scores [B,L,L]
__device__ float g_q[BB * CC * LL];
__device__ float g_k[BB * CC * LL];
__device__ float g_v[BB * CC * LL];
__device__ float g_s[(size_t)BB * LL * LL];

// ---------------------------------------------------------------------------
// Kernel 1: QKV projection.  out[b, o, l] = sum_i W[o,i] * x[b,i,l] + bias[o]
// Tiled SGEMM: BM=64 (o), BN=64 (l), BK=16 (i), 256 threads, 4x4 per thread.
// blockIdx.z = b*3 + w  (w: 0=q, 1=k, 2=v)
// ---------------------------------------------------------------------------
__global__ __launch_bounds__(256) void proj_kernel(
    const float* __restrict__ x,
    const float* __restrict__ Wq, const float* __restrict__ bq,
    const float* __restrict__ Wk, const float* __restrict__ bk,
    const float* __restrict__ Wv, const float* __restrict__ bv)
{
    const int BM = 64, BN = 64, BK = 16;
    __shared__ float As[BK][BM + 4];   // As[k][m] = W[m0+m, k0+k]
    __shared__ float Bs[BK][BN + 4];   // Bs[k][n] = X[k0+k, n0+n]

    int z = blockIdx.z;
    int b = z / 3, w = z % 3;
    const float* W    = (w == 0) ? Wq : (w == 1) ? Wk : Wv;
    const float* bias = (w == 0) ? bq : (w == 1) ? bk : bv;
    float* out        = (w == 0) ? g_q : (w == 1) ? g_k : g_v;
    const float* X = x + (size_t)b * CC * LL;
    out += (size_t)b * CC * LL;

    int m0 = blockIdx.y * BM;
    int n0 = blockIdx.x * BN;
    int tid = threadIdx.x;
    int ty = tid / 16, tx = tid % 16;

    float acc[4][4] = {};

    for (int k0 = 0; k0 < CC; k0 += BK) {
        // W tile [64 x 16] -> transposed into As[k][m]
        {
            int row  = tid / 4;           // 0..63 (m)
            int col4 = (tid % 4) * 4;     // 0,4,8,12 (k)
            float4 v4 = *(const float4*)&W[(size_t)(m0 + row) * CC + k0 + col4];
            As[col4 + 0][row] = v4.x;
            As[col4 + 1][row] = v4.y;
            As[col4 + 2][row] = v4.z;
            As[col4 + 3][row] = v4.w;
        }
        // X tile [16 x 64] -> Bs[k][n]
        {
            int row  = tid / 16;          // 0..15 (k)
            int col4 = (tid % 16) * 4;    // 0..60 (n)
            *(float4*)&Bs[row][col4] =
                *(const float4*)&X[(size_t)(k0 + row) * LL + n0 + col4];
        }
        __syncthreads();
        #pragma unroll
        for (int k = 0; k < BK; k++) {
            float4 a4 = *(const float4*)&As[k][ty * 4];
            float4 b4 = *(const float4*)&Bs[k][tx * 4];
            float a[4] = {a4.x, a4.y, a4.z, a4.w};
            float bb[4] = {b4.x, b4.y, b4.z, b4.w};
            #pragma unroll
            for (int i = 0; i < 4; i++)
                #pragma unroll
                for (int j = 0; j < 4; j++)
                    acc[i][j] = fmaf(a[i], bb[j], acc[i][j]);
        }
        __syncthreads();
    }

    #pragma unroll
    for (int i = 0; i < 4; i++) {
        int m = m0 + ty * 4 + i;
        float bi = bias[m];
        #pragma unroll
        for (int j = 0; j < 4; j++)
            out[(size_t)m * LL + n0 + tx * 4 + j] = acc[i][j] + bi;
    }
}

// ---------------------------------------------------------------------------
// Kernel 2: scores[b, l, m] = scale * sum_c q[b,c,l] * k[b,c,m]
// Both operands are K-major in memory (c is the leading/row dim), so both
// tiles load straight into [k][n] layout with coalesced float4 loads.
// ---------------------------------------------------------------------------
__global__ __launch_bounds__(256) void scores_kernel()
{
    const int BM = 64, BN = 64, BK = 16;
    __shared__ float Qs[BK][BM + 4];
    __shared__ float Ks[BK][BN + 4];

    int b = blockIdx.z;
    const float* Q = g_q + (size_t)b * CC * LL;
    const float* K = g_k + (size_t)b * CC * LL;
    float* S = g_s + (size_t)b * LL * LL;

    int m0 = blockIdx.y * BM;   // l
    int n0 = blockIdx.x * BN;   // m
    int tid = threadIdx.x;
    int ty = tid / 16, tx = tid % 16;
    const float scale = 0.044194173824159216f;  // 1/sqrt(512)

    float acc[4][4] = {};

    for (int k0 = 0; k0 < CC; k0 += BK) {
        int row  = tid / 16;          // 0..15 (c)
        int col4 = (tid % 16) * 4;    // 0..60
        *(float4*)&Qs[row][col4] =
            *(const float4*)&Q[(size_t)(k0 + row) * LL + m0 + col4];
        *(float4*)&Ks[row][col4] =
            *(const float4*)&K[(size_t)(k0 + row) * LL + n0 + col4];
        __syncthreads();
        #pragma unroll
        for (int k = 0; k < BK; k++) {
            float4 a4 = *(const float4*)&Qs[k][ty * 4];
            float4 b4 = *(const float4*)&Ks[k][tx * 4];
            float a[4] = {a4.x, a4.y, a4.z, a4.w};
            float bb[4] = {b4.x, b4.y, b4.z, b4.w};
            #pragma unroll
            for (int i = 0; i < 4; i++)
                #pragma unroll
                for (int j = 0; j < 4; j++)
                    acc[i][j] = fmaf(a[i], bb[j], acc[i][j]);
        }
        __syncthreads();
    }

    #pragma unroll
    for (int i = 0; i < 4; i++) {
        size_t l = m0 + ty * 4 + i;
        #pragma unroll
        for (int j = 0; j < 4; j++)
            S[l * LL + n0 + tx * 4 + j] = acc[i][j] * scale;
    }
}

// ---------------------------------------------------------------------------
// Kernel 3: row softmax over last dim (L=2048), in place in g_s.
// One block (256 threads) per row; each thread owns 8 strided elements.
// ---------------------------------------------------------------------------
__global__ __launch_bounds__(256) void softmax_kernel()
{
    size_t row = blockIdx.x;
    float* p = g_s + row * (size_t)LL;
    int t = threadIdx.x;
    int w = t >> 5, lane = t & 31;

    float v[8];
    float mx = -1e30f;
    #pragma unroll
    for (int i = 0; i < 8; i++) {
        v[i] = p[t + i * 256];
        mx = fmaxf(mx, v[i]);
    }
    #pragma unroll
    for (int o = 16; o > 0; o >>= 1)
        mx = fmaxf(mx, __shfl_xor_sync(0xFFFFFFFFu, mx, o));

    __shared__ float smax[8], ssum[8];
    if (lane == 0) smax[w] = mx;
    __syncthreads();
    mx = fmaxf(fmaxf(fmaxf(smax[0], smax[1]), fmaxf(smax[2], smax[3])),
               fmaxf(fmaxf(smax[4], smax[5]), fmaxf(smax[6], smax[7])));

    float sum = 0.f;
    #pragma unroll
    for (int i = 0; i < 8; i++) {
        v[i] = __expf(v[i] - mx);
        sum += v[i];
    }
    #pragma unroll
    for (int o = 16; o > 0; o >>= 1)
        sum += __shfl_xor_sync(0xFFFFFFFFu, sum, o);
    if (lane == 0) ssum[w] = sum;
    __syncthreads();
    sum = (ssum[0] + ssum[1]) + (ssum[2] + ssum[3]) +
          (ssum[4] + ssum[5]) + (ssum[6] + ssum[7]);

    float inv = 1.0f / sum;
    #pragma unroll
    for (int i = 0; i < 8; i++)
        p[t + i * 256] = v[i] * inv;
}

// ---------------------------------------------------------------------------
// Kernel 4: out[b, c, l] = sum_m v[b,c,m] * attn[b,l,m]
// A = V[b] [C, L] (c rows, m cols)  -> As[k=m][c]   (transposed store)
// B = attn [L, L] (l rows, m cols)  -> Bs[k=m][l]   (transposed store)
// ---------------------------------------------------------------------------
__global__ __launch_bounds__(256) void out_kernel(float* __restrict__ out)
{
    const int BM = 64, BN = 64, BK = 16;
    __shared__ float As[BK][BM + 4];
    __shared__ float Bs[BK][BN + 4];

    int b = blockIdx.z;
    const float* V = g_v + (size_t)b * CC * LL;
    const float* A = g_s + (size_t)b * LL * LL;
    float* O = out + (size_t)b * CC * LL;

    int m0 = blockIdx.y * BM;   // c
    int n0 = blockIdx.x * BN;   // l
    int tid = threadIdx.x;
    int ty = tid / 16, tx = tid % 16;

    float acc[4][4] = {};

    for (int k0 = 0; k0 < LL; k0 += BK) {
        {   // V tile [64c x 16m] -> As[m][c]
            int row  = tid / 4;
            int col4 = (tid % 4) * 4;
            float4 v4 = *(const float4*)&V[(size_t)(m0 + row) * LL + k0 + col4];
            As[col4 + 0][row] = v4.x;
            As[col4 + 1][row] = v4.y;
            As[col4 + 2][row] = v4.z;
            As[col4 + 3][row] = v4.w;
        }
        {   // attn tile [64l x 16m] -> Bs[m][l]
            int row  = tid / 4;
            int col4 = (tid % 4) * 4;
            float4 v4 = *(const float4*)&A[(size_t)(n0 + row) * LL + k0 + col4];
            Bs[col4 + 0][row] = v4.x;
            Bs[col4 + 1][row] = v4.y;
            Bs[col4 + 2][row] = v4.z;
            Bs[col4 + 3][row] = v4.w;
        }
        __syncthreads();
        #pragma unroll
        for (int k = 0; k < BK; k++) {
            float4 a4 = *(const float4*)&As[k][ty * 4];
            float4 b4 = *(const float4*)&Bs[k][tx * 4];
            float a[4] = {a4.x, a4.y, a4.z, a4.w};
            float bb[4] = {b4.x, b4.y, b4.z, b4.w};
            #pragma unroll
            for (int i = 0; i < 4; i++)
                #pragma unroll
                for (int j = 0; j < 4; j++)
                    acc[i][j] = fmaf(a[i], bb[j], acc[i][j]);
        }
        __syncthreads();
    }

    #pragma unroll
    for (int i = 0; i < 4; i++) {
        int c = m0 + ty * 4 + i;
        #pragma unroll
        for (int j = 0; j < 4; j++)
            O[(size_t)c * LL + n0 + tx * 4 + j] = acc[i][j];
    }
}

// ---------------------------------------------------------------------------
extern "C" void kernel_launch(void* const* d_in, const int* in_sizes, int n_in,
                              void* d_out, int out_size)
{
    const float* x  = (const float*)d_in[0];
    const float* Wq = (const float*)d_in[1];
    const float* bq = (const float*)d_in[2];
    const float* Wk = (const float*)d_in[3];
    const float* bk = (const float*)d_in[4];
    const float* Wv = (const float*)d_in[5];
    const float* bv = (const float*)d_in[6];
    float* out = (float*)d_out;

    dim3 blk(256);

    // QKV projections: grid (L/64, C/64, 3*B)
    proj_kernel<<<dim3(LL / 64, CC / 64, 3 * BB), blk>>>(x, Wq, bq, Wk, bk, Wv, bv);

    // scores: grid (L/64, L/64, B)
    scores_kernel<<<dim3(LL / 64, LL / 64, BB), blk>>>();

    // softmax: one block per (b, l) row
    softmax_kernel<<<dim3(BB * LL), blk>>>();

    // out: grid (L/64, C/64, B)
    out_kernel<<<dim3(LL / 64, CC / 64, BB), blk>>>(out);
}

// round 2
// speedup vs baseline: 1.2564x; 1.2564x over previous
#include <cuda_runtime.h>
#include <math.h>

#define BB 8
#define CC 512
#define LL 2048

#define BM 128
#define BN 128
#define BK 16
#define SPAD 4
#define SW (BM + SPAD)

// Scratch: q,k,v [B,C,L] and scores [B,L,L]
__device__ float g_q[BB * CC * LL];
__device__ float g_k[BB * CC * LL];
__device__ float g_v[BB * CC * LL];
__device__ float g_s[(size_t)BB * LL * LL];

// ---------------------------------------------------------------------------
// Shared inner product: 8x8 microtile split as 2x2 blocks of 4x4 at stride 64.
// a-frag rows: {ty*4+i, 64+ty*4+i}; b-frag cols: {tx*4+j, 64+tx*4+j}.
// ---------------------------------------------------------------------------
__device__ __forceinline__ void mma_tile(
    const float (*As)[SW], const float (*Bs)[SW],
    int ty, int tx, float acc[8][8])
{
    #pragma unroll
    for (int k = 0; k < BK; k++) {
        float a[8], b[8];
        *(float4*)&a[0] = *(const float4*)&As[k][ty * 4];
        *(float4*)&a[4] = *(const float4*)&As[k][64 + ty * 4];
        *(float4*)&b[0] = *(const float4*)&Bs[k][tx * 4];
        *(float4*)&b[4] = *(const float4*)&Bs[k][64 + tx * 4];
        #pragma unroll
        for (int i = 0; i < 8; i++)
            #pragma unroll
            for (int j = 0; j < 8; j++)
                acc[i][j] = fmaf(a[i], b[j], acc[i][j]);
    }
}

// ---------------------------------------------------------------------------
// Kernel 1: QKV projection.  out[b, o, l] = sum_i W[o,i] * x[b,i,l] + bias[o]
// A = W [C,C] row-major (k contiguous) -> transposed scatter into As[k][m]
// B = X [C,L] (n contiguous along l)   -> straight into Bs[k][n]
// ---------------------------------------------------------------------------
__global__ __launch_bounds__(256, 2) void proj_kernel(
    const float* __restrict__ x,
    const float* __restrict__ Wq, const float* __restrict__ bq,
    const float* __restrict__ Wk, const float* __restrict__ bk,
    const float* __restrict__ Wv, const float* __restrict__ bv)
{
    __shared__ float As[BK][SW];
    __shared__ float Bs[BK][SW];

    int z = blockIdx.z;
    int b = z / 3, w = z % 3;
    const float* W    = (w == 0) ? Wq : (w == 1) ? Wk : Wv;
    const float* bias = (w == 0) ? bq : (w == 1) ? bk : bv;
    float* out        = (w == 0) ? g_q : (w == 1) ? g_k : g_v;
    const float* X = x + (size_t)b * CC * LL;
    out += (size_t)b * CC * LL;

    int m0 = blockIdx.y * BM;
    int n0 = blockIdx.x * BN;
    int tid = threadIdx.x;
    int ty = tid >> 4, tx = tid & 15;

    // A load geometry (transposed): row m = tid/2, k-half = (tid&1)*8
    int arow = tid >> 1;
    int akh  = (tid & 1) * 8;
    // B load geometry (straight): k row = tid/16, col = (tid&15)*8
    int brow = tid >> 4;
    int bcol = (tid & 15) * 8;

    float asta[8];
    float4 bsta0, bsta1;

    // prologue: stage tile 0
    *(float4*)&asta[0] = *(const float4*)&W[(size_t)(m0 + arow) * CC + akh];
    *(float4*)&asta[4] = *(const float4*)&W[(size_t)(m0 + arow) * CC + akh + 4];
    bsta0 = *(const float4*)&X[(size_t)brow * LL + n0 + bcol];
    bsta1 = *(const float4*)&X[(size_t)brow * LL + n0 + bcol + 4];

    float acc[8][8] = {};
    const int NT = CC / BK;

    for (int t = 0; t < NT; t++) {
        #pragma unroll
        for (int kk = 0; kk < 8; kk++)
            As[akh + kk][arow] = asta[kk];
        *(float4*)&Bs[brow][bcol]     = bsta0;
        *(float4*)&Bs[brow][bcol + 4] = bsta1;
        __syncthreads();

        if (t + 1 < NT) {
            int k0 = (t + 1) * BK;
            *(float4*)&asta[0] = *(const float4*)&W[(size_t)(m0 + arow) * CC + k0 + akh];
            *(float4*)&asta[4] = *(const float4*)&W[(size_t)(m0 + arow) * CC + k0 + akh + 4];
            bsta0 = *(const float4*)&X[(size_t)(k0 + brow) * LL + n0 + bcol];
            bsta1 = *(const float4*)&X[(size_t)(k0 + brow) * LL + n0 + bcol + 4];
        }

        mma_tile(As, Bs, ty, tx, acc);
        __syncthreads();
    }

    #pragma unroll
    for (int ri = 0; ri < 2; ri++)
        #pragma unroll
        for (int i = 0; i < 4; i++) {
            int m = m0 + ri * 64 + ty * 4 + i;
            float bi = bias[m];
            float* dst = &out[(size_t)m * LL + n0];
            float4 v0, v1;
            v0.x = acc[ri*4+i][0] + bi; v0.y = acc[ri*4+i][1] + bi;
            v0.z = acc[ri*4+i][2] + bi; v0.w = acc[ri*4+i][3] + bi;
            v1.x = acc[ri*4+i][4] + bi; v1.y = acc[ri*4+i][5] + bi;
            v1.z = acc[ri*4+i][6] + bi; v1.w = acc[ri*4+i][7] + bi;
            *(float4*)&dst[tx * 4]      = v0;
            *(float4*)&dst[64 + tx * 4] = v1;
        }
}

// ---------------------------------------------------------------------------
// Kernel 2: scores[b, l, m] = scale * sum_c q[b,c,l] * k[b,c,m]
// Both operands c-major (k contiguous rows) -> straight loads for both tiles.
// ---------------------------------------------------------------------------
__global__ __launch_bounds__(256, 2) void scores_kernel()
{
    __shared__ float Qs[BK][SW];
    __shared__ float Ks[BK][SW];

    int b = blockIdx.z;
    const float* Q = g_q + (size_t)b * CC * LL;
    const float* K = g_k + (size_t)b * CC * LL;
    float* S = g_s + (size_t)b * LL * LL;

    int m0 = blockIdx.y * BM;   // l
    int n0 = blockIdx.x * BN;   // m
    int tid = threadIdx.x;
    int ty = tid >> 4, tx = tid & 15;
    const float scale = 0.044194173824159216f;  // 1/sqrt(512)

    int lrow = tid >> 4;          // k 0..15
    int lcol = (tid & 15) * 8;

    float4 qa, qb, ka, kb;
    qa = *(const float4*)&Q[(size_t)lrow * LL + m0 + lcol];
    qb = *(const float4*)&Q[(size_t)lrow * LL + m0 + lcol + 4];
    ka = *(const float4*)&K[(size_t)lrow * LL + n0 + lcol];
    kb = *(const float4*)&K[(size_t)lrow * LL + n0 + lcol + 4];

    float acc[8][8] = {};
    const int NT = CC / BK;

    for (int t = 0; t < NT; t++) {
        *(float4*)&Qs[lrow][lcol]     = qa;
        *(float4*)&Qs[lrow][lcol + 4] = qb;
        *(float4*)&Ks[lrow][lcol]     = ka;
        *(float4*)&Ks[lrow][lcol + 4] = kb;
        __syncthreads();

        if (t + 1 < NT) {
            int k0 = (t + 1) * BK;
            qa = *(const float4*)&Q[(size_t)(k0 + lrow) * LL + m0 + lcol];
            qb = *(const float4*)&Q[(size_t)(k0 + lrow) * LL + m0 + lcol + 4];
            ka = *(const float4*)&K[(size_t)(k0 + lrow) * LL + n0 + lcol];
            kb = *(const float4*)&K[(size_t)(k0 + lrow) * LL + n0 + lcol + 4];
        }

        mma_tile(Qs, Ks, ty, tx, acc);
        __syncthreads();
    }

    #pragma unroll
    for (int ri = 0; ri < 2; ri++)
        #pragma unroll
        for (int i = 0; i < 4; i++) {
            size_t l = m0 + ri * 64 + ty * 4 + i;
            float* dst = &S[l * LL + n0];
            float4 v0, v1;
            v0.x = acc[ri*4+i][0] * scale; v0.y = acc[ri*4+i][1] * scale;
            v0.z = acc[ri*4+i][2] * scale; v0.w = acc[ri*4+i][3] * scale;
            v1.x = acc[ri*4+i][4] * scale; v1.y = acc[ri*4+i][5] * scale;
            v1.z = acc[ri*4+i][6] * scale; v1.w = acc[ri*4+i][7] * scale;
            *(float4*)&dst[tx * 4]      = v0;
            *(float4*)&dst[64 + tx * 4] = v1;
        }
}

// ---------------------------------------------------------------------------
// Kernel 3: row softmax over last dim (L=2048), in place in g_s.
// ---------------------------------------------------------------------------
__global__ __launch_bounds__(256) void softmax_kernel()
{
    size_t row = blockIdx.x;
    float* p = g_s + row * (size_t)LL;
    int t = threadIdx.x;
    int w = t >> 5, lane = t & 31;

    float v[8];
    float mx = -1e30f;
    #pragma unroll
    for (int i = 0; i < 8; i++) {
        v[i] = p[t + i * 256];
        mx = fmaxf(mx, v[i]);
    }
    #pragma unroll
    for (int o = 16; o > 0; o >>= 1)
        mx = fmaxf(mx, __shfl_xor_sync(0xFFFFFFFFu, mx, o));

    __shared__ float smax[8], ssum[8];
    if (lane == 0) smax[w] = mx;
    __syncthreads();
    mx = fmaxf(fmaxf(fmaxf(smax[0], smax[1]), fmaxf(smax[2], smax[3])),
               fmaxf(fmaxf(smax[4], smax[5]), fmaxf(smax[6], smax[7])));

    float sum = 0.f;
    #pragma unroll
    for (int i = 0; i < 8; i++) {
        v[i] = __expf(v[i] - mx);
        sum += v[i];
    }
    #pragma unroll
    for (int o = 16; o > 0; o >>= 1)
        sum += __shfl_xor_sync(0xFFFFFFFFu, sum, o);
    if (lane == 0) ssum[w] = sum;
    __syncthreads();
    sum = (ssum[0] + ssum[1]) + (ssum[2] + ssum[3]) +
          (ssum[4] + ssum[5]) + (ssum[6] + ssum[7]);

    float inv = 1.0f / sum;
    #pragma unroll
    for (int i = 0; i < 8; i++)
        p[t + i * 256] = v[i] * inv;
}

// ---------------------------------------------------------------------------
// Kernel 4: out[b, c, l] = sum_m v[b,c,m] * attn[b,l,m]
// A = V [C,L] (k=m contiguous) -> transposed scatter into As[k][c]
// B = attn [L,L] (k=m contiguous) -> transposed scatter into Bs[k][l]
// ---------------------------------------------------------------------------
__global__ __launch_bounds__(256, 2) void out_kernel(float* __restrict__ out)
{
    __shared__ float As[BK][SW];
    __shared__ float Bs[BK][SW];

    int b = blockIdx.z;
    const float* V = g_v + (size_t)b * CC * LL;
    const float* A = g_s + (size_t)b * LL * LL;
    float* O = out + (size_t)b * CC * LL;

    int m0 = blockIdx.y * BM;   // c
    int n0 = blockIdx.x * BN;   // l
    int tid = threadIdx.x;
    int ty = tid >> 4, tx = tid & 15;

    int row = tid >> 1;        // 0..127
    int kh  = (tid & 1) * 8;   // 0 or 8

    float asta[8], bsta[8];
    *(float4*)&asta[0] = *(const float4*)&V[(size_t)(m0 + row) * LL + kh];
    *(float4*)&asta[4] = *(const float4*)&V[(size_t)(m0 + row) * LL + kh + 4];
    *(float4*)&bsta[0] = *(const float4*)&A[(size_t)(n0 + row) * LL + kh];
    *(float4*)&bsta[4] = *(const float4*)&A[(size_t)(n0 + row) * LL + kh + 4];

    float acc[8][8] = {};
    const int NT = LL / BK;

    for (int t = 0; t < NT; t++) {
        #pragma unroll
        for (int kk = 0; kk < 8; kk++) {
            As[kh + kk][row] = asta[kk];
            Bs[kh + kk][row] = bsta[kk];
        }
        __syncthreads();

        if (t + 1 < NT) {
            int k0 = (t + 1) * BK;
            *(float4*)&asta[0] = *(const float4*)&V[(size_t)(m0 + row) * LL + k0 + kh];
            *(float4*)&asta[4] = *(const float4*)&V[(size_t)(m0 + row) * LL + k0 + kh + 4];
            *(float4*)&bsta[0] = *(const float4*)&A[(size_t)(n0 + row) * LL + k0 + kh];
            *(float4*)&bsta[4] = *(const float4*)&A[(size_t)(n0 + row) * LL + k0 + kh + 4];
        }

        mma_tile(As, Bs, ty, tx, acc);
        __syncthreads();
    }

    #pragma unroll
    for (int ri = 0; ri < 2; ri++)
        #pragma unroll
        for (int i = 0; i < 4; i++) {
            int c = m0 + ri * 64 + ty * 4 + i;
            float* dst = &O[(size_t)c * LL + n0];
            float4 v0, v1;
            v0.x = acc[ri*4+i][0]; v0.y = acc[ri*4+i][1];
            v0.z = acc[ri*4+i][2]; v0.w = acc[ri*4+i][3];
            v1.x = acc[ri*4+i][4]; v1.y = acc[ri*4+i][5];
            v1.z = acc[ri*4+i][6]; v1.w = acc[ri*4+i][7];
            *(float4*)&dst[tx * 4]      = v0;
            *(float4*)&dst[64 + tx * 4] = v1;
        }
}

// ---------------------------------------------------------------------------
extern "C" void kernel_launch(void* const* d_in, const int* in_sizes, int n_in,
                              void* d_out, int out_size)
{
    const float* x  = (const float*)d_in[0];
    const float* Wq = (const float*)d_in[1];
    const float* bq = (const float*)d_in[2];
    const float* Wk = (const float*)d_in[3];
    const float* bk = (const float*)d_in[4];
    const float* Wv = (const float*)d_in[5];
    const float* bv = (const float*)d_in[6];
    float* out = (float*)d_out;

    dim3 blk(256);

    proj_kernel<<<dim3(LL / BN, CC / BM, 3 * BB), blk>>>(x, Wq, bq, Wk, bk, Wv, bv);
    scores_kernel<<<dim3(LL / BN, LL / BM, BB), blk>>>();
    softmax_kernel<<<dim3(BB * LL), blk>>>();
    out_kernel<<<dim3(LL / BN, CC / BM, BB), blk>>>(out);
}

// round 4
// speedup vs baseline: 2.8839x; 2.2953x over previous
#include <cuda_runtime.h>
#include <cuda_bf16.h>
#include <cstdint>

#define BB 8
#define CC 512
#define LL 2048

// ---------------------------------------------------------------------------
// Device scratch (hi/lo bf16 splits)
// ---------------------------------------------------------------------------
__device__ __nv_bfloat16 g_xt_hi[(size_t)BB * LL * CC];   // x^T [b][l][c]
__device__ __nv_bfloat16 g_xt_lo[(size_t)BB * LL * CC];
__device__ __nv_bfloat16 g_w_hi[3 * CC * CC];             // W   [w][c_out][c_in]
__device__ __nv_bfloat16 g_w_lo[3 * CC * CC];
__device__ __nv_bfloat16 g_qt_hi[(size_t)BB * LL * CC];   // q^T [b][l][c]
__device__ __nv_bfloat16 g_qt_lo[(size_t)BB * LL * CC];
__device__ __nv_bfloat16 g_kt_hi[(size_t)BB * LL * CC];   // k^T [b][m][c]
__device__ __nv_bfloat16 g_kt_lo[(size_t)BB * LL * CC];
__device__ __nv_bfloat16 g_v_hi[(size_t)BB * CC * LL];    // v   [b][c][m]
__device__ __nv_bfloat16 g_v_lo[(size_t)BB * CC * LL];
__device__ float         g_s[(size_t)BB * LL * LL];       // scores fp32 [b][l][m]
__device__ __nv_bfloat16 g_a_hi[(size_t)BB * LL * LL];    // attn [b][l][m]
__device__ __nv_bfloat16 g_a_lo[(size_t)BB * LL * LL];

// ---------------------------------------------------------------------------
// Helpers (baseline PTX only: mma.sync / ldmatrix / cp.async — no 103a feats)
// ---------------------------------------------------------------------------
__device__ __forceinline__ uint32_t smem_u32(const void* p) {
    uint32_t a;
    asm("{ .reg .u64 t; cvta.to.shared.u64 t, %1; cvt.u32.u64 %0, t; }"
        : "=r"(a) : "l"(p));
    return a;
}

__device__ __forceinline__ void ldsm4(uint32_t* r, uint32_t addr) {
    asm volatile("ldmatrix.sync.aligned.m8n8.x4.shared.b16 {%0,%1,%2,%3}, [%4];"
                 : "=r"(r[0]), "=r"(r[1]), "=r"(r[2]), "=r"(r[3]) : "r"(addr));
}

__device__ __forceinline__ void mma16816(float* c, const uint32_t* a, const uint32_t* b) {
    asm volatile(
        "mma.sync.aligned.m16n8k16.row.col.f32.bf16.bf16.f32 "
        "{%0,%1,%2,%3}, {%4,%5,%6,%7}, {%8,%9}, {%0,%1,%2,%3};"
        : "+f"(c[0]), "+f"(c[1]), "+f"(c[2]), "+f"(c[3])
        : "r"(a[0]), "r"(a[1]), "r"(a[2]), "r"(a[3]), "r"(b[0]), "r"(b[1]));
}

#define CP16(dst, src) \
    asm volatile("cp.async.cg.shared.global [%0], [%1], 16;" :: "r"(dst), "l"(src))
#define CP_COMMIT() asm volatile("cp.async.commit_group;" ::: "memory")
#define CP_WAIT0()  asm volatile("cp.async.wait_group 0;" ::: "memory")

__device__ __forceinline__ void split2(float v, __nv_bfloat16& hi, __nv_bfloat16& lo) {
    hi = __float2bfloat16(v);
    lo = __float2bfloat16(v - __bfloat162float(hi));
}

// ---------------------------------------------------------------------------
// Conversion kernels
// ---------------------------------------------------------------------------
__global__ __launch_bounds__(256) void conv_w(
    const float* __restrict__ Wq, const float* __restrict__ Wk,
    const float* __restrict__ Wv)
{
    int idx = blockIdx.x * 256 + threadIdx.x;
    int wsel = idx >> 18;
    int off = idx & 262143;
    const float* W = (wsel == 0) ? Wq : (wsel == 1) ? Wk : Wv;
    __nv_bfloat16 hi, lo;
    split2(W[off], hi, lo);
    g_w_hi[idx] = hi;
    g_w_lo[idx] = lo;
}

__global__ __launch_bounds__(256) void conv_x(const float* __restrict__ x)
{
    __shared__ float ts[32][33];
    int b = blockIdx.z, c0 = blockIdx.y * 32, l0 = blockIdx.x * 32;
    int lane = threadIdx.x & 31, wrp = threadIdx.x >> 5;
    const float* X = x + ((size_t)b * CC + c0) * LL + l0;
    #pragma unroll
    for (int ii = 0; ii < 4; ii++)
        ts[wrp + 8 * ii][lane] = X[(size_t)(wrp + 8 * ii) * LL + lane];
    __syncthreads();
    size_t base = ((size_t)b * LL + l0) * CC + c0;
    #pragma unroll
    for (int ii = 0; ii < 4; ii++) {
        int lr = wrp + 8 * ii;
        __nv_bfloat16 hi, lo;
        split2(ts[lane][lr], hi, lo);
        g_xt_hi[base + (size_t)lr * CC + lane] = hi;
        g_xt_lo[base + (size_t)lr * CC + lane] = lo;
    }
}

// ---------------------------------------------------------------------------
// mma.sync bf16-split GEMM: CTA 128x128, 8 warps of 64x32, BK=32, double buf.
// Smem tile: 128 rows x 40 bf16 (80B row, 16B-aligned, ldmatrix conflict-free)
// Stage layout: Ah@0  Al@10240  Bh@20480  Bl@30720 ; stage stride 40960.
// MODE 0: proj (wsel<2: D[l][c]=x_t*W^T ; wsel=2: D[c][l]=W*x_t^T)
// MODE 1: scores D[l][m] = q_t * k_t^T  -> g_s fp32 * scale
// MODE 2: out   D[c][l] = v * attn^T    -> output fp32
// ---------------------------------------------------------------------------
#define SMEM_DYN 81920
#define T_AH 0
#define T_AL 10240
#define T_BH 20480
#define T_BL 30720
#define STG  40960

__device__ __forceinline__ void cp_tile(uint32_t dst_base,
    const __nv_bfloat16* __restrict__ g, int row0, int ld, int k0, int tid)
{
    #pragma unroll
    for (int i = 0; i < 2; i++) {
        int idx = i * 256 + tid;
        int r = idx >> 2, u = idx & 3;
        uint32_t dst = dst_base + (uint32_t)r * 80u + (uint32_t)u * 16u;
        const __nv_bfloat16* src = g + (size_t)(row0 + r) * ld + k0 + u * 8;
        CP16(dst, src);
    }
}

__device__ __forceinline__ void mma_block(float* acc, const uint32_t* af, const uint32_t* bf)
{
    #pragma unroll
    for (int i = 0; i < 4; i++)
        #pragma unroll
        for (int j = 0; j < 4; j++)
            mma16816(acc + (i * 4 + j) * 4, af + i * 4, bf + (j >> 1) * 4 + (j & 1) * 2);
}

template <int MODE>
__global__ __launch_bounds__(256, 2) void gemm_kernel(
    const float* __restrict__ bq, const float* __restrict__ bk,
    const float* __restrict__ bv, float* __restrict__ outp)
{
    extern __shared__ char smem[];
    const uint32_t sb = smem_u32(smem);
    const int tid = threadIdx.x;
    const int lane = tid & 31, wid = tid >> 5;
    const int wm = wid & 1, wn = wid >> 1;

    const __nv_bfloat16 *Ah, *Al, *Bh, *Bl;
    int lda, ldb, NT, m0, n0, b, wsel = 0;

    if (MODE == 0) {
        int id = blockIdx.x;
        b = blockIdx.y / 3; wsel = blockIdx.y % 3;
        if (wsel < 2) {
            m0 = (id >> 2) * 128; n0 = (id & 3) * 128;           // m=l, n=c_out
            Ah = g_xt_hi + (size_t)b * LL * CC; Al = g_xt_lo + (size_t)b * LL * CC;
            Bh = g_w_hi + (size_t)wsel * CC * CC; Bl = g_w_lo + (size_t)wsel * CC * CC;
        } else {
            m0 = (id & 3) * 128; n0 = (id >> 2) * 128;           // m=c_out, n=l
            Ah = g_w_hi + (size_t)2 * CC * CC; Al = g_w_lo + (size_t)2 * CC * CC;
            Bh = g_xt_hi + (size_t)b * LL * CC; Bl = g_xt_lo + (size_t)b * LL * CC;
        }
        lda = CC; ldb = CC; NT = CC / 32;
    } else if (MODE == 1) {
        b = blockIdx.y;
        m0 = (blockIdx.x >> 4) * 128; n0 = (blockIdx.x & 15) * 128;
        Ah = g_qt_hi + (size_t)b * LL * CC; Al = g_qt_lo + (size_t)b * LL * CC;
        Bh = g_kt_hi + (size_t)b * LL * CC; Bl = g_kt_lo + (size_t)b * LL * CC;
        lda = CC; ldb = CC; NT = CC / 32;
    } else {
        b = blockIdx.y;
        m0 = (blockIdx.x & 3) * 128; n0 = (blockIdx.x >> 2) * 128;  // m=c, n=l
        Ah = g_v_hi + (size_t)b * CC * LL; Al = g_v_lo + (size_t)b * CC * LL;
        Bh = g_a_hi + (size_t)b * LL * LL; Bl = g_a_lo + (size_t)b * LL * LL;
        lda = LL; ldb = LL; NT = LL / 32;
    }

    // per-thread ldmatrix base offsets within a tile
    const uint32_t aoff = (uint32_t)((wm * 64 + (lane & 15)) * 80 + ((lane >> 4) * 16));
    const uint32_t boff = (uint32_t)((wn * 32 + (((lane >> 3) >> 1) * 8) + (lane & 7)) * 80
                                     + ((lane >> 3) & 1) * 16);

    float acc[64];
    #pragma unroll
    for (int i = 0; i < 64; i++) acc[i] = 0.f;

    // prologue
    cp_tile(sb + T_AH, Ah, m0, lda, 0, tid);
    cp_tile(sb + T_AL, Al, m0, lda, 0, tid);
    cp_tile(sb + T_BH, Bh, n0, ldb, 0, tid);
    cp_tile(sb + T_BL, Bl, n0, ldb, 0, tid);
    CP_COMMIT();

    for (int t = 0; t < NT; t++) {
        CP_WAIT0();
        __syncthreads();
        if (t + 1 < NT) {
            uint32_t nb = sb + ((t + 1) & 1) * STG;
            int k0 = (t + 1) * 32;
            cp_tile(nb + T_AH, Ah, m0, lda, k0, tid);
            cp_tile(nb + T_AL, Al, m0, lda, k0, tid);
            cp_tile(nb + T_BH, Bh, n0, ldb, k0, tid);
            cp_tile(nb + T_BL, Bl, n0, ldb, k0, tid);
            CP_COMMIT();
        }
        const uint32_t base = sb + (t & 1) * STG;
        #pragma unroll
        for (int ks = 0; ks < 2; ks++) {
            const uint32_t kb = ks * 32;   // 16 bf16 = 32 bytes
            uint32_t af[16], bh[8], bl[8];
            #pragma unroll
            for (int i = 0; i < 4; i++) ldsm4(af + i * 4, base + T_AH + aoff + i * 1280 + kb);
            #pragma unroll
            for (int jp = 0; jp < 2; jp++) ldsm4(bh + jp * 4, base + T_BH + boff + jp * 1280 + kb);
            mma_block(acc, af, bh);                 // hi * hi
            #pragma unroll
            for (int jp = 0; jp < 2; jp++) ldsm4(bl + jp * 4, base + T_BL + boff + jp * 1280 + kb);
            mma_block(acc, af, bl);                 // hi * lo
            #pragma unroll
            for (int i = 0; i < 4; i++) ldsm4(af + i * 4, base + T_AL + aoff + i * 1280 + kb);
            mma_block(acc, af, bh);                 // lo * hi
        }
    }

    // ---------------- epilogue ----------------
    const int mb = m0 + wm * 64;
    const int nb = n0 + wn * 32;

    if (MODE == 0) {
        if (wsel < 2) {
            const float* bias = (wsel == 0) ? bq : bk;
            __nv_bfloat16* H  = ((wsel == 0) ? g_qt_hi : g_kt_hi) + (size_t)b * LL * CC;
            __nv_bfloat16* Lo = ((wsel == 0) ? g_qt_lo : g_kt_lo) + (size_t)b * LL * CC;
            #pragma unroll
            for (int i = 0; i < 4; i++) {
                int r0 = mb + i * 16 + (lane >> 2);
                #pragma unroll
                for (int j = 0; j < 4; j++) {
                    const float* c = acc + (i * 4 + j) * 4;
                    int nn = nb + j * 8 + (lane & 3) * 2;
                    float b0 = bias[nn], b1 = bias[nn + 1];
                    __nv_bfloat16 h0, l0, h1, l1;
                    split2(c[0] + b0, h0, l0); split2(c[1] + b1, h1, l1);
                    *(__nv_bfloat162*)(H + (size_t)r0 * CC + nn)  = __nv_bfloat162(h0, h1);
                    *(__nv_bfloat162*)(Lo + (size_t)r0 * CC + nn) = __nv_bfloat162(l0, l1);
                    split2(c[2] + b0, h0, l0); split2(c[3] + b1, h1, l1);
                    *(__nv_bfloat162*)(H + (size_t)(r0 + 8) * CC + nn)  = __nv_bfloat162(h0, h1);
                    *(__nv_bfloat162*)(Lo + (size_t)(r0 + 8) * CC + nn) = __nv_bfloat162(l0, l1);
                }
            }
        } else {
            __nv_bfloat16* H  = g_v_hi + (size_t)b * CC * LL;
            __nv_bfloat16* Lo = g_v_lo + (size_t)b * CC * LL;
            #pragma unroll
            for (int i = 0; i < 4; i++) {
                int r0 = mb + i * 16 + (lane >> 2);
                float bi0 = bv[r0], bi8 = bv[r0 + 8];
                #pragma unroll
                for (int j = 0; j < 4; j++) {
                    const float* c = acc + (i * 4 + j) * 4;
                    int nn = nb + j * 8 + (lane & 3) * 2;
                    __nv_bfloat16 h0, l0, h1, l1;
                    split2(c[0] + bi0, h0, l0); split2(c[1] + bi0, h1, l1);
                    *(__nv_bfloat162*)(H + (size_t)r0 * LL + nn)  = __nv_bfloat162(h0, h1);
                    *(__nv_bfloat162*)(Lo + (size_t)r0 * LL + nn) = __nv_bfloat162(l0, l1);
                    split2(c[2] + bi8, h0, l0); split2(c[3] + bi8, h1, l1);
                    *(__nv_bfloat162*)(H + (size_t)(r0 + 8) * LL + nn)  = __nv_bfloat162(h0, h1);
                    *(__nv_bfloat162*)(Lo + (size_t)(r0 + 8) * LL + nn) = __nv_bfloat162(l0, l1);
                }
            }
        }
    } else if (MODE == 1) {
        const float scale = 0.044194173824159216f;  // 1/sqrt(512)
        float* S = g_s + (size_t)b * LL * LL;
        #pragma unroll
        for (int i = 0; i < 4; i++) {
            int r0 = mb + i * 16 + (lane >> 2);
            #pragma unroll
            for (int j = 0; j < 4; j++) {
                const float* c = acc + (i * 4 + j) * 4;
                int nn = nb + j * 8 + (lane & 3) * 2;
                float2 v0 = {c[0] * scale, c[1] * scale};
                float2 v1 = {c[2] * scale, c[3] * scale};
                *(float2*)&S[(size_t)r0 * LL + nn]       = v0;
                *(float2*)&S[(size_t)(r0 + 8) * LL + nn] = v1;
            }
        }
    } else {
        float* O = outp + (size_t)b * CC * LL;
        #pragma unroll
        for (int i = 0; i < 4; i++) {
            int r0 = mb + i * 16 + (lane >> 2);
            #pragma unroll
            for (int j = 0; j < 4; j++) {
                const float* c = acc + (i * 4 + j) * 4;
                int nn = nb + j * 8 + (lane & 3) * 2;
                float2 v0 = {c[0], c[1]};
                float2 v1 = {c[2], c[3]};
                *(float2*)&O[(size_t)r0 * LL + nn]       = v0;
                *(float2*)&O[(size_t)(r0 + 8) * LL + nn] = v1;
            }
        }
    }
}

// ---------------------------------------------------------------------------
// softmax over last dim of g_s, fused bf16 hi/lo split output
// ---------------------------------------------------------------------------
__global__ __launch_bounds__(256) void softmax_kernel()
{
    size_t rowi = blockIdx.x;
    const float* p = g_s + rowi * (size_t)LL;
    int t = threadIdx.x;
    int w = t >> 5, lane = t & 31;

    float v[8];
    float mx = -1e30f;
    #pragma unroll
    for (int i = 0; i < 8; i++) {
        v[i] = p[t + i * 256];
        mx = fmaxf(mx, v[i]);
    }
    #pragma unroll
    for (int o = 16; o > 0; o >>= 1)
        mx = fmaxf(mx, __shfl_xor_sync(0xFFFFFFFFu, mx, o));

    __shared__ float smax[8], ssum[8];
    if (lane == 0) smax[w] = mx;
    __syncthreads();
    mx = fmaxf(fmaxf(fmaxf(smax[0], smax[1]), fmaxf(smax[2], smax[3])),
               fmaxf(fmaxf(smax[4], smax[5]), fmaxf(smax[6], smax[7])));

    float sum = 0.f;
    #pragma unroll
    for (int i = 0; i < 8; i++) {
        v[i] = __expf(v[i] - mx);
        sum += v[i];
    }
    #pragma unroll
    for (int o = 16; o > 0; o >>= 1)
        sum += __shfl_xor_sync(0xFFFFFFFFu, sum, o);
    if (lane == 0) ssum[w] = sum;
    __syncthreads();
    sum = (ssum[0] + ssum[1]) + (ssum[2] + ssum[3]) +
          (ssum[4] + ssum[5]) + (ssum[6] + ssum[7]);

    float inv = 1.0f / sum;
    size_t base = rowi * (size_t)LL;
    #pragma unroll
    for (int i = 0; i < 8; i++) {
        __nv_bfloat16 hi, lo;
        split2(v[i] * inv, hi, lo);
        g_a_hi[base + t + i * 256] = hi;
        g_a_lo[base + t + i * 256] = lo;
    }
}

// ---------------------------------------------------------------------------
extern "C" void kernel_launch(void* const* d_in, const int* in_sizes, int n_in,
                              void* d_out, int out_size)
{
    const float* x  = (const float*)d_in[0];
    const float* Wq = (const float*)d_in[1];
    const float* bq = (const float*)d_in[2];
    const float* Wk = (const float*)d_in[3];
    const float* bk = (const float*)d_in[4];
    const float* Wv = (const float*)d_in[5];
    const float* bv = (const float*)d_in[6];
    float* out = (float*)d_out;

    cudaFuncSetAttribute(gemm_kernel<0>, cudaFuncAttributeMaxDynamicSharedMemorySize, SMEM_DYN);
    cudaFuncSetAttribute(gemm_kernel<1>, cudaFuncAttributeMaxDynamicSharedMemorySize, SMEM_DYN);
    cudaFuncSetAttribute(gemm_kernel<2>, cudaFuncAttributeMaxDynamicSharedMemorySize, SMEM_DYN);

    conv_w<<<3 * CC * CC / 256, 256>>>(Wq, Wk, Wv);
    conv_x<<<dim3(LL / 32, CC / 32, BB), 256>>>(x);

    gemm_kernel<0><<<dim3(64, 3 * BB), 256, SMEM_DYN>>>(bq, bk, bv, out);
    gemm_kernel<1><<<dim3(256, BB), 256, SMEM_DYN>>>(bq, bk, bv, out);
    softmax_kernel<<<BB * LL, 256>>>();
    gemm_kernel<2><<<dim3(64, BB), 256, SMEM_DYN>>>(bq, bk, bv, out);
}

// round 5
// speedup vs baseline: 3.7066x; 1.2853x over previous
#include <cuda_runtime.h>
#include <cuda_bf16.h>
#include <cuda_fp16.h>
#include <cstdint>

#define BB 8
#define CC 512
#define LL 2048

// ---------------------------------------------------------------------------
// Device scratch
// ---------------------------------------------------------------------------
__device__ __nv_bfloat16 g_xt_hi[(size_t)BB * LL * CC];   // x^T [b][l][c]
__device__ __nv_bfloat16 g_xt_lo[(size_t)BB * LL * CC];
__device__ __nv_bfloat16 g_w_hi[3 * CC * CC];             // W   [w][c_out][c_in]
__device__ __nv_bfloat16 g_w_lo[3 * CC * CC];
__device__ __nv_bfloat16 g_qt_hi[(size_t)BB * LL * CC];   // q^T [b][l][c]
__device__ __nv_bfloat16 g_qt_lo[(size_t)BB * LL * CC];
__device__ __nv_bfloat16 g_kt_hi[(size_t)BB * LL * CC];   // k^T [b][m][c]
__device__ __nv_bfloat16 g_kt_lo[(size_t)BB * LL * CC];
__device__ __half        g_v16[(size_t)BB * CC * LL];     // v   [b][c][m] fp16
__device__ float         g_s[(size_t)BB * LL * LL];       // scores fp32 [b][l][m]
__device__ __half        g_a16[(size_t)BB * LL * LL];     // attn [b][l][m] fp16

// ---------------------------------------------------------------------------
// Helpers (baseline PTX only)
// ---------------------------------------------------------------------------
__device__ __forceinline__ uint32_t smem_u32(const void* p) {
    uint32_t a;
    asm("{ .reg .u64 t; cvta.to.shared.u64 t, %1; cvt.u32.u64 %0, t; }"
        : "=r"(a) : "l"(p));
    return a;
}

__device__ __forceinline__ void ldsm4(uint32_t* r, uint32_t addr) {
    asm volatile("ldmatrix.sync.aligned.m8n8.x4.shared.b16 {%0,%1,%2,%3}, [%4];"
                 : "=r"(r[0]), "=r"(r[1]), "=r"(r[2]), "=r"(r[3]) : "r"(addr));
}

__device__ __forceinline__ void mma16816(float* c, const uint32_t* a, const uint32_t* b) {
    asm volatile(
        "mma.sync.aligned.m16n8k16.row.col.f32.bf16.bf16.f32 "
        "{%0,%1,%2,%3}, {%4,%5,%6,%7}, {%8,%9}, {%0,%1,%2,%3};"
        : "+f"(c[0]), "+f"(c[1]), "+f"(c[2]), "+f"(c[3])
        : "r"(a[0]), "r"(a[1]), "r"(a[2]), "r"(a[3]), "r"(b[0]), "r"(b[1]));
}

__device__ __forceinline__ void mma16816h(float* c, const uint32_t* a, const uint32_t* b) {
    asm volatile(
        "mma.sync.aligned.m16n8k16.row.col.f32.f16.f16.f32 "
        "{%0,%1,%2,%3}, {%4,%5,%6,%7}, {%8,%9}, {%0,%1,%2,%3};"
        : "+f"(c[0]), "+f"(c[1]), "+f"(c[2]), "+f"(c[3])
        : "r"(a[0]), "r"(a[1]), "r"(a[2]), "r"(a[3]), "r"(b[0]), "r"(b[1]));
}

#define CP16(dst, src) \
    asm volatile("cp.async.cg.shared.global [%0], [%1], 16;" :: "r"(dst), "l"(src))
#define CP_COMMIT() asm volatile("cp.async.commit_group;" ::: "memory")
#define CP_WAIT0()  asm volatile("cp.async.wait_group 0;" ::: "memory")

__device__ __forceinline__ void split2(float v, __nv_bfloat16& hi, __nv_bfloat16& lo) {
    hi = __float2bfloat16(v);
    lo = __float2bfloat16(v - __bfloat162float(hi));
}

// ---------------------------------------------------------------------------
// Conversion kernels
// ---------------------------------------------------------------------------
__global__ __launch_bounds__(256) void conv_w(
    const float* __restrict__ Wq, const float* __restrict__ Wk,
    const float* __restrict__ Wv)
{
    int idx = blockIdx.x * 256 + threadIdx.x;
    int wsel = idx >> 18;
    int off = idx & 262143;
    const float* W = (wsel == 0) ? Wq : (wsel == 1) ? Wk : Wv;
    __nv_bfloat16 hi, lo;
    split2(W[off], hi, lo);
    g_w_hi[idx] = hi;
    g_w_lo[idx] = lo;
}

__global__ __launch_bounds__(256) void conv_x(const float* __restrict__ x)
{
    __shared__ float ts[32][33];
    int b = blockIdx.z, c0 = blockIdx.y * 32, l0 = blockIdx.x * 32;
    int lane = threadIdx.x & 31, wrp = threadIdx.x >> 5;
    const float* X = x + ((size_t)b * CC + c0) * LL + l0;
    #pragma unroll
    for (int ii = 0; ii < 4; ii++)
        ts[wrp + 8 * ii][lane] = X[(size_t)(wrp + 8 * ii) * LL + lane];
    __syncthreads();
    size_t base = ((size_t)b * LL + l0) * CC + c0;
    #pragma unroll
    for (int ii = 0; ii < 4; ii++) {
        int lr = wrp + 8 * ii;
        __nv_bfloat16 hi, lo;
        split2(ts[lane][lr], hi, lo);
        g_xt_hi[base + (size_t)lr * CC + lane] = hi;
        g_xt_lo[base + (size_t)lr * CC + lane] = lo;
    }
}

// ---------------------------------------------------------------------------
// bf16-split GEMM (proj + scores): CTA 128x128, 8 warps 64x32, BK=32, 2 stages
// Smem rows padded to 80B for conflict-free ldmatrix.
// MODE 0: proj (wsel<2: D[l][c]=x_t*W^T -> q_t/k_t split ; wsel=2: v fp16)
// MODE 1: scores D[l][m] = q_t * k_t^T -> g_s fp32 * scale
// ---------------------------------------------------------------------------
#define SMEM_DYN 81920
#define T_AH 0
#define T_AL 10240
#define T_BH 20480
#define T_BL 30720
#define STG  40960

__device__ __forceinline__ void cp_tile(uint32_t dst_base,
    const void* __restrict__ gv, int row0, int ld, int k0, int tid)
{
    const __nv_bfloat16* g = (const __nv_bfloat16*)gv;
    #pragma unroll
    for (int i = 0; i < 2; i++) {
        int idx = i * 256 + tid;
        int r = idx >> 2, u = idx & 3;
        uint32_t dst = dst_base + (uint32_t)r * 80u + (uint32_t)u * 16u;
        const __nv_bfloat16* src = g + (size_t)(row0 + r) * ld + k0 + u * 8;
        CP16(dst, src);
    }
}

__device__ __forceinline__ void mma_block(float* acc, const uint32_t* af, const uint32_t* bf)
{
    #pragma unroll
    for (int i = 0; i < 4; i++)
        #pragma unroll
        for (int j = 0; j < 4; j++)
            mma16816(acc + (i * 4 + j) * 4, af + i * 4, bf + (j >> 1) * 4 + (j & 1) * 2);
}

__device__ __forceinline__ void mma_block_h(float* acc, const uint32_t* af, const uint32_t* bf)
{
    #pragma unroll
    for (int i = 0; i < 4; i++)
        #pragma unroll
        for (int j = 0; j < 4; j++)
            mma16816h(acc + (i * 4 + j) * 4, af + i * 4, bf + (j >> 1) * 4 + (j & 1) * 2);
}

template <int MODE>
__global__ __launch_bounds__(256, 2) void gemm_kernel(
    const float* __restrict__ bq, const float* __restrict__ bk,
    const float* __restrict__ bv)
{
    extern __shared__ char smem[];
    const uint32_t sb = smem_u32(smem);
    const int tid = threadIdx.x;
    const int lane = tid & 31, wid = tid >> 5;
    const int wm = wid & 1, wn = wid >> 1;

    const __nv_bfloat16 *Ah, *Al, *Bh, *Bl;
    int lda, ldb, NT, m0, n0, b, wsel = 0;

    if (MODE == 0) {
        int id = blockIdx.x;
        b = blockIdx.y / 3; wsel = blockIdx.y % 3;
        if (wsel < 2) {
            m0 = (id >> 2) * 128; n0 = (id & 3) * 128;           // m=l, n=c_out
            Ah = g_xt_hi + (size_t)b * LL * CC; Al = g_xt_lo + (size_t)b * LL * CC;
            Bh = g_w_hi + (size_t)wsel * CC * CC; Bl = g_w_lo + (size_t)wsel * CC * CC;
        } else {
            m0 = (id & 3) * 128; n0 = (id >> 2) * 128;           // m=c_out, n=l
            Ah = g_w_hi + (size_t)2 * CC * CC; Al = g_w_lo + (size_t)2 * CC * CC;
            Bh = g_xt_hi + (size_t)b * LL * CC; Bl = g_xt_lo + (size_t)b * LL * CC;
        }
        lda = CC; ldb = CC; NT = CC / 32;
    } else {
        b = blockIdx.y;
        m0 = (blockIdx.x >> 4) * 128; n0 = (blockIdx.x & 15) * 128;
        Ah = g_qt_hi + (size_t)b * LL * CC; Al = g_qt_lo + (size_t)b * LL * CC;
        Bh = g_kt_hi + (size_t)b * LL * CC; Bl = g_kt_lo + (size_t)b * LL * CC;
        lda = CC; ldb = CC; NT = CC / 32;
    }

    const uint32_t aoff = (uint32_t)((wm * 64 + (lane & 15)) * 80 + ((lane >> 4) * 16));
    const uint32_t boff = (uint32_t)((wn * 32 + (((lane >> 3) >> 1) * 8) + (lane & 7)) * 80
                                     + ((lane >> 3) & 1) * 16);

    float acc[64];
    #pragma unroll
    for (int i = 0; i < 64; i++) acc[i] = 0.f;

    cp_tile(sb + T_AH, Ah, m0, lda, 0, tid);
    cp_tile(sb + T_AL, Al, m0, lda, 0, tid);
    cp_tile(sb + T_BH, Bh, n0, ldb, 0, tid);
    cp_tile(sb + T_BL, Bl, n0, ldb, 0, tid);
    CP_COMMIT();

    for (int t = 0; t < NT; t++) {
        CP_WAIT0();
        __syncthreads();
        if (t + 1 < NT) {
            uint32_t nb = sb + ((t + 1) & 1) * STG;
            int k0 = (t + 1) * 32;
            cp_tile(nb + T_AH, Ah, m0, lda, k0, tid);
            cp_tile(nb + T_AL, Al, m0, lda, k0, tid);
            cp_tile(nb + T_BH, Bh, n0, ldb, k0, tid);
            cp_tile(nb + T_BL, Bl, n0, ldb, k0, tid);
            CP_COMMIT();
        }
        const uint32_t base = sb + (t & 1) * STG;
        #pragma unroll
        for (int ks = 0; ks < 2; ks++) {
            const uint32_t kb = ks * 32;
            uint32_t af[16], bh[8], bl[8];
            #pragma unroll
            for (int i = 0; i < 4; i++) ldsm4(af + i * 4, base + T_AH + aoff + i * 1280 + kb);
            #pragma unroll
            for (int jp = 0; jp < 2; jp++) ldsm4(bh + jp * 4, base + T_BH + boff + jp * 1280 + kb);
            mma_block(acc, af, bh);                 // hi * hi
            #pragma unroll
            for (int jp = 0; jp < 2; jp++) ldsm4(bl + jp * 4, base + T_BL + boff + jp * 1280 + kb);
            mma_block(acc, af, bl);                 // hi * lo
            #pragma unroll
            for (int i = 0; i < 4; i++) ldsm4(af + i * 4, base + T_AL + aoff + i * 1280 + kb);
            mma_block(acc, af, bh);                 // lo * hi
        }
    }

    const int mb = m0 + wm * 64;
    const int nb = n0 + wn * 32;

    if (MODE == 0) {
        if (wsel < 2) {
            const float* bias = (wsel == 0) ? bq : bk;
            __nv_bfloat16* H  = ((wsel == 0) ? g_qt_hi : g_kt_hi) + (size_t)b * LL * CC;
            __nv_bfloat16* Lo = ((wsel == 0) ? g_qt_lo : g_kt_lo) + (size_t)b * LL * CC;
            #pragma unroll
            for (int i = 0; i < 4; i++) {
                int r0 = mb + i * 16 + (lane >> 2);
                #pragma unroll
                for (int j = 0; j < 4; j++) {
                    const float* c = acc + (i * 4 + j) * 4;
                    int nn = nb + j * 8 + (lane & 3) * 2;
                    float b0 = bias[nn], b1 = bias[nn + 1];
                    __nv_bfloat16 h0, l0, h1, l1;
                    split2(c[0] + b0, h0, l0); split2(c[1] + b1, h1, l1);
                    *(__nv_bfloat162*)(H + (size_t)r0 * CC + nn)  = __nv_bfloat162(h0, h1);
                    *(__nv_bfloat162*)(Lo + (size_t)r0 * CC + nn) = __nv_bfloat162(l0, l1);
                    split2(c[2] + b0, h0, l0); split2(c[3] + b1, h1, l1);
                    *(__nv_bfloat162*)(H + (size_t)(r0 + 8) * CC + nn)  = __nv_bfloat162(h0, h1);
                    *(__nv_bfloat162*)(Lo + (size_t)(r0 + 8) * CC + nn) = __nv_bfloat162(l0, l1);
                }
            }
        } else {
            __half* V = g_v16 + (size_t)b * CC * LL;
            #pragma unroll
            for (int i = 0; i < 4; i++) {
                int r0 = mb + i * 16 + (lane >> 2);
                float bi0 = bv[r0], bi8 = bv[r0 + 8];
                #pragma unroll
                for (int j = 0; j < 4; j++) {
                    const float* c = acc + (i * 4 + j) * 4;
                    int nn = nb + j * 8 + (lane & 3) * 2;
                    *(__half2*)(V + (size_t)r0 * LL + nn) =
                        __floats2half2_rn(c[0] + bi0, c[1] + bi0);
                    *(__half2*)(V + (size_t)(r0 + 8) * LL + nn) =
                        __floats2half2_rn(c[2] + bi8, c[3] + bi8);
                }
            }
        }
    } else {
        const float scale = 0.044194173824159216f;  // 1/sqrt(512)
        float* S = g_s + (size_t)b * LL * LL;
        #pragma unroll
        for (int i = 0; i < 4; i++) {
            int r0 = mb + i * 16 + (lane >> 2);
            #pragma unroll
            for (int j = 0; j < 4; j++) {
                const float* c = acc + (i * 4 + j) * 4;
                int nn = nb + j * 8 + (lane & 3) * 2;
                float2 v0 = {c[0] * scale, c[1] * scale};
                float2 v1 = {c[2] * scale, c[3] * scale};
                *(float2*)&S[(size_t)r0 * LL + nn]       = v0;
                *(float2*)&S[(size_t)(r0 + 8) * LL + nn] = v1;
            }
        }
    }
}

// ---------------------------------------------------------------------------
// out = V * P^T, single-product fp16 MMA. CTA 128x128, BK=32, 2 stages.
// Stage: A(v fp16)@0, B(p fp16)@10240; stride 20480; total 40960.
// ---------------------------------------------------------------------------
#define SMEM_DYN2 40960
#define STG2 20480

__global__ __launch_bounds__(256, 2) void out_kernel(float* __restrict__ outp)
{
    extern __shared__ char smem[];
    const uint32_t sb = smem_u32(smem);
    const int tid = threadIdx.x;
    const int lane = tid & 31, wid = tid >> 5;
    const int wm = wid & 1, wn = wid >> 1;

    const int b = blockIdx.y;
    const int m0 = (blockIdx.x & 3) * 128;     // c
    const int n0 = (blockIdx.x >> 2) * 128;    // l
    const __half* V = g_v16 + (size_t)b * CC * LL;
    const __half* P = g_a16 + (size_t)b * LL * LL;
    const int NT = LL / 32;

    const uint32_t aoff = (uint32_t)((wm * 64 + (lane & 15)) * 80 + ((lane >> 4) * 16));
    const uint32_t boff = (uint32_t)((wn * 32 + (((lane >> 3) >> 1) * 8) + (lane & 7)) * 80
                                     + ((lane >> 3) & 1) * 16);

    float acc[64];
    #pragma unroll
    for (int i = 0; i < 64; i++) acc[i] = 0.f;

    cp_tile(sb + 0,     V, m0, LL, 0, tid);
    cp_tile(sb + 10240, P, n0, LL, 0, tid);
    CP_COMMIT();

    for (int t = 0; t < NT; t++) {
        CP_WAIT0();
        __syncthreads();
        if (t + 1 < NT) {
            uint32_t nb = sb + ((t + 1) & 1) * STG2;
            int k0 = (t + 1) * 32;
            cp_tile(nb + 0,     V, m0, LL, k0, tid);
            cp_tile(nb + 10240, P, n0, LL, k0, tid);
            CP_COMMIT();
        }
        const uint32_t base = sb + (t & 1) * STG2;
        #pragma unroll
        for (int ks = 0; ks < 2; ks++) {
            const uint32_t kb = ks * 32;
            uint32_t af[16], bf[8];
            #pragma unroll
            for (int i = 0; i < 4; i++) ldsm4(af + i * 4, base + aoff + i * 1280 + kb);
            #pragma unroll
            for (int jp = 0; jp < 2; jp++) ldsm4(bf + jp * 4, base + 10240 + boff + jp * 1280 + kb);
            mma_block_h(acc, af, bf);
        }
    }

    const int mb = m0 + wm * 64;
    const int nb = n0 + wn * 32;
    float* O = outp + (size_t)b * CC * LL;
    #pragma unroll
    for (int i = 0; i < 4; i++) {
        int r0 = mb + i * 16 + (lane >> 2);
        #pragma unroll
        for (int j = 0; j < 4; j++) {
            const float* c = acc + (i * 4 + j) * 4;
            int nn = nb + j * 8 + (lane & 3) * 2;
            float2 v0 = {c[0], c[1]};
            float2 v1 = {c[2], c[3]};
            *(float2*)&O[(size_t)r0 * LL + nn]       = v0;
            *(float2*)&O[(size_t)(r0 + 8) * LL + nn] = v1;
        }
    }
}

// ---------------------------------------------------------------------------
// softmax over last dim of g_s, fp16 output
// ---------------------------------------------------------------------------
__global__ __launch_bounds__(256) void softmax_kernel()
{
    size_t rowi = blockIdx.x;
    const float* p = g_s + rowi * (size_t)LL;
    int t = threadIdx.x;
    int w = t >> 5, lane = t & 31;

    float v[8];
    float mx = -1e30f;
    #pragma unroll
    for (int i = 0; i < 8; i++) {
        v[i] = p[t + i * 256];
        mx = fmaxf(mx, v[i]);
    }
    #pragma unroll
    for (int o = 16; o > 0; o >>= 1)
        mx = fmaxf(mx, __shfl_xor_sync(0xFFFFFFFFu, mx, o));

    __shared__ float smax[8], ssum[8];
    if (lane == 0) smax[w] = mx;
    __syncthreads();
    mx = fmaxf(fmaxf(fmaxf(smax[0], smax[1]), fmaxf(smax[2], smax[3])),
               fmaxf(fmaxf(smax[4], smax[5]), fmaxf(smax[6], smax[7])));

    float sum = 0.f;
    #pragma unroll
    for (int i = 0; i < 8; i++) {
        v[i] = __expf(v[i] - mx);
        sum += v[i];
    }
    #pragma unroll
    for (int o = 16; o > 0; o >>= 1)
        sum += __shfl_xor_sync(0xFFFFFFFFu, sum, o);
    if (lane == 0) ssum[w] = sum;
    __syncthreads();
    sum = (ssum[0] + ssum[1]) + (ssum[2] + ssum[3]) +
          (ssum[4] + ssum[5]) + (ssum[6] + ssum[7]);

    float inv = 1.0f / sum;
    size_t base = rowi * (size_t)LL;
    #pragma unroll
    for (int i = 0; i < 8; i++)
        g_a16[base + t + i * 256] = __float2half(v[i] * inv);
}

// ---------------------------------------------------------------------------
extern "C" void kernel_launch(void* const* d_in, const int* in_sizes, int n_in,
                              void* d_out, int out_size)
{
    const float* x  = (const float*)d_in[0];
    const float* Wq = (const float*)d_in[1];
    const float* bq = (const float*)d_in[2];
    const float* Wk = (const float*)d_in[3];
    const float* bk = (const float*)d_in[4];
    const float* Wv = (const float*)d_in[5];
    const float* bv = (const float*)d_in[6];
    float* out = (float*)d_out;

    cudaFuncSetAttribute(gemm_kernel<0>, cudaFuncAttributeMaxDynamicSharedMemorySize, SMEM_DYN);
    cudaFuncSetAttribute(gemm_kernel<1>, cudaFuncAttributeMaxDynamicSharedMemorySize, SMEM_DYN);
    cudaFuncSetAttribute(out_kernel, cudaFuncAttributeMaxDynamicSharedMemorySize, SMEM_DYN2);

    conv_w<<<3 * CC * CC / 256, 256>>>(Wq, Wk, Wv);
    conv_x<<<dim3(LL / 32, CC / 32, BB), 256>>>(x);

    gemm_kernel<0><<<dim3(64, 3 * BB), 256, SMEM_DYN>>>(bq, bk, bv);
    gemm_kernel<1><<<dim3(256, BB), 256, SMEM_DYN>>>(bq, bk, bv);
    softmax_kernel<<<BB * LL, 256>>>();
    out_kernel<<<dim3(64, BB), 256, SMEM_DYN2>>>(out);
}

// round 6
// speedup vs baseline: 5.1290x; 1.3838x over previous
#include <cuda_runtime.h>
#include <cuda_bf16.h>
#include <cuda_fp16.h>
#include <cstdint>

#define BB 8
#define CC 512
#define LL 2048

// ---------------------------------------------------------------------------
// Device scratch
// ---------------------------------------------------------------------------
__device__ __nv_bfloat16 g_xt_hi[(size_t)BB * LL * CC];   // x^T [b][l][c]
__device__ __nv_bfloat16 g_xt_lo[(size_t)BB * LL * CC];
__device__ __nv_bfloat16 g_w_hi[3 * CC * CC];             // W   [w][c_out][c_in]
__device__ __nv_bfloat16 g_w_lo[3 * CC * CC];
__device__ __half        g_qt16[(size_t)BB * LL * CC];    // q^T [b][l][c] fp16
__device__ __half        g_kt16[(size_t)BB * LL * CC];    // k^T [b][m][c] fp16
__device__ __half        g_v16[(size_t)BB * CC * LL];     // v   [b][c][m] fp16
__device__ __half        g_e16[(size_t)BB * LL * LL];     // e^s [b][l][m] fp16
__device__ float         g_psum[(size_t)BB * LL * 16];    // partial row sums
__device__ float         g_rinv[(size_t)BB * LL];         // 1 / row sum

// ---------------------------------------------------------------------------
// Helpers (baseline PTX only)
// ---------------------------------------------------------------------------
__device__ __forceinline__ uint32_t smem_u32(const void* p) {
    uint32_t a;
    asm("{ .reg .u64 t; cvta.to.shared.u64 t, %1; cvt.u32.u64 %0, t; }"
        : "=r"(a) : "l"(p));
    return a;
}

__device__ __forceinline__ void ldsm4(uint32_t* r, uint32_t addr) {
    asm volatile("ldmatrix.sync.aligned.m8n8.x4.shared.b16 {%0,%1,%2,%3}, [%4];"
                 : "=r"(r[0]), "=r"(r[1]), "=r"(r[2]), "=r"(r[3]) : "r"(addr));
}

__device__ __forceinline__ void mma16816(float* c, const uint32_t* a, const uint32_t* b) {
    asm volatile(
        "mma.sync.aligned.m16n8k16.row.col.f32.bf16.bf16.f32 "
        "{%0,%1,%2,%3}, {%4,%5,%6,%7}, {%8,%9}, {%0,%1,%2,%3};"
        : "+f"(c[0]), "+f"(c[1]), "+f"(c[2]), "+f"(c[3])
        : "r"(a[0]), "r"(a[1]), "r"(a[2]), "r"(a[3]), "r"(b[0]), "r"(b[1]));
}

__device__ __forceinline__ void mma16816h(float* c, const uint32_t* a, const uint32_t* b) {
    asm volatile(
        "mma.sync.aligned.m16n8k16.row.col.f32.f16.f16.f32 "
        "{%0,%1,%2,%3}, {%4,%5,%6,%7}, {%8,%9}, {%0,%1,%2,%3};"
        : "+f"(c[0]), "+f"(c[1]), "+f"(c[2]), "+f"(c[3])
        : "r"(a[0]), "r"(a[1]), "r"(a[2]), "r"(a[3]), "r"(b[0]), "r"(b[1]));
}

#define CP16(dst, src) \
    asm volatile("cp.async.cg.shared.global [%0], [%1], 16;" :: "r"(dst), "l"(src))
#define CP_COMMIT() asm volatile("cp.async.commit_group;" ::: "memory")
#define CP_WAIT0()  asm volatile("cp.async.wait_group 0;" ::: "memory")

__device__ __forceinline__ void split2(float v, __nv_bfloat16& hi, __nv_bfloat16& lo) {
    hi = __float2bfloat16(v);
    lo = __float2bfloat16(v - __bfloat162float(hi));
}

// ---------------------------------------------------------------------------
// Conversion kernels
// ---------------------------------------------------------------------------
__global__ __launch_bounds__(256) void conv_w(
    const float* __restrict__ Wq, const float* __restrict__ Wk,
    const float* __restrict__ Wv)
{
    int idx = blockIdx.x * 256 + threadIdx.x;
    int wsel = idx >> 18;
    int off = idx & 262143;
    const float* W = (wsel == 0) ? Wq : (wsel == 1) ? Wk : Wv;
    __nv_bfloat16 hi, lo;
    split2(W[off], hi, lo);
    g_w_hi[idx] = hi;
    g_w_lo[idx] = lo;
}

__global__ __launch_bounds__(256) void conv_x(const float* __restrict__ x)
{
    __shared__ float ts[32][33];
    int b = blockIdx.z, c0 = blockIdx.y * 32, l0 = blockIdx.x * 32;
    int lane = threadIdx.x & 31, wrp = threadIdx.x >> 5;
    const float* X = x + ((size_t)b * CC + c0) * LL + l0;
    #pragma unroll
    for (int ii = 0; ii < 4; ii++)
        ts[wrp + 8 * ii][lane] = X[(size_t)(wrp + 8 * ii) * LL + lane];
    __syncthreads();
    size_t base = ((size_t)b * LL + l0) * CC + c0;
    #pragma unroll
    for (int ii = 0; ii < 4; ii++) {
        int lr = wrp + 8 * ii;
        __nv_bfloat16 hi, lo;
        split2(ts[lane][lr], hi, lo);
        g_xt_hi[base + (size_t)lr * CC + lane] = hi;
        g_xt_lo[base + (size_t)lr * CC + lane] = lo;
    }
}

// ---------------------------------------------------------------------------
// Common tile copier: 128 rows x 32 2-byte elements (64B) per tile, 80B pitch
// ---------------------------------------------------------------------------
__device__ __forceinline__ void cp_tile(uint32_t dst_base,
    const void* __restrict__ gv, int row0, int ld, int k0, int tid)
{
    const __nv_bfloat16* g = (const __nv_bfloat16*)gv;
    #pragma unroll
    for (int i = 0; i < 2; i++) {
        int idx = i * 256 + tid;
        int r = idx >> 2, u = idx & 3;
        uint32_t dst = dst_base + (uint32_t)r * 80u + (uint32_t)u * 16u;
        const __nv_bfloat16* src = g + (size_t)(row0 + r) * ld + k0 + u * 8;
        CP16(dst, src);
    }
}

__device__ __forceinline__ void mma_block(float* acc, const uint32_t* af, const uint32_t* bf)
{
    #pragma unroll
    for (int i = 0; i < 4; i++)
        #pragma unroll
        for (int j = 0; j < 4; j++)
            mma16816(acc + (i * 4 + j) * 4, af + i * 4, bf + (j >> 1) * 4 + (j & 1) * 2);
}

__device__ __forceinline__ void mma_block_h(float* acc, const uint32_t* af, const uint32_t* bf)
{
    #pragma unroll
    for (int i = 0; i < 4; i++)
        #pragma unroll
        for (int j = 0; j < 4; j++)
            mma16816h(acc + (i * 4 + j) * 4, af + i * 4, bf + (j >> 1) * 4 + (j & 1) * 2);
}

// ---------------------------------------------------------------------------
// proj: bf16-split GEMM. wsel<2: D[l][c]=x_t*W^T -> q/k fp16 ; wsel=2: v fp16
// ---------------------------------------------------------------------------
#define SMEM_DYN 81920
#define T_AH 0
#define T_AL 10240
#define T_BH 20480
#define T_BL 30720
#define STG  40960

__global__ __launch_bounds__(256, 2) void proj_kernel(
    const float* __restrict__ bq, const float* __restrict__ bk,
    const float* __restrict__ bv)
{
    extern __shared__ char smem[];
    const uint32_t sb = smem_u32(smem);
    const int tid = threadIdx.x;
    const int lane = tid & 31, wid = tid >> 5;
    const int wm = wid & 1, wn = wid >> 1;

    const __nv_bfloat16 *Ah, *Al, *Bh, *Bl;
    int m0, n0;
    int id = blockIdx.x;
    int b = blockIdx.y / 3, wsel = blockIdx.y % 3;
    if (wsel < 2) {
        m0 = (id >> 2) * 128; n0 = (id & 3) * 128;           // m=l, n=c_out
        Ah = g_xt_hi + (size_t)b * LL * CC; Al = g_xt_lo + (size_t)b * LL * CC;
        Bh = g_w_hi + (size_t)wsel * CC * CC; Bl = g_w_lo + (size_t)wsel * CC * CC;
    } else {
        m0 = (id & 3) * 128; n0 = (id >> 2) * 128;           // m=c_out, n=l
        Ah = g_w_hi + (size_t)2 * CC * CC; Al = g_w_lo + (size_t)2 * CC * CC;
        Bh = g_xt_hi + (size_t)b * LL * CC; Bl = g_xt_lo + (size_t)b * LL * CC;
    }
    const int NT = CC / 32;

    const uint32_t aoff = (uint32_t)((wm * 64 + (lane & 15)) * 80 + ((lane >> 4) * 16));
    const uint32_t boff = (uint32_t)((wn * 32 + (((lane >> 3) >> 1) * 8) + (lane & 7)) * 80
                                     + ((lane >> 3) & 1) * 16);

    float acc[64];
    #pragma unroll
    for (int i = 0; i < 64; i++) acc[i] = 0.f;

    cp_tile(sb + T_AH, Ah, m0, CC, 0, tid);
    cp_tile(sb + T_AL, Al, m0, CC, 0, tid);
    cp_tile(sb + T_BH, Bh, n0, CC, 0, tid);
    cp_tile(sb + T_BL, Bl, n0, CC, 0, tid);
    CP_COMMIT();

    for (int t = 0; t < NT; t++) {
        CP_WAIT0();
        __syncthreads();
        if (t + 1 < NT) {
            uint32_t nb = sb + ((t + 1) & 1) * STG;
            int k0 = (t + 1) * 32;
            cp_tile(nb + T_AH, Ah, m0, CC, k0, tid);
            cp_tile(nb + T_AL, Al, m0, CC, k0, tid);
            cp_tile(nb + T_BH, Bh, n0, CC, k0, tid);
            cp_tile(nb + T_BL, Bl, n0, CC, k0, tid);
            CP_COMMIT();
        }
        const uint32_t base = sb + (t & 1) * STG;
        #pragma unroll
        for (int ks = 0; ks < 2; ks++) {
            const uint32_t kb = ks * 32;
            uint32_t af[16], bh[8], bl[8];
            #pragma unroll
            for (int i = 0; i < 4; i++) ldsm4(af + i * 4, base + T_AH + aoff + i * 1280 + kb);
            #pragma unroll
            for (int jp = 0; jp < 2; jp++) ldsm4(bh + jp * 4, base + T_BH + boff + jp * 1280 + kb);
            mma_block(acc, af, bh);                 // hi * hi
            #pragma unroll
            for (int jp = 0; jp < 2; jp++) ldsm4(bl + jp * 4, base + T_BL + boff + jp * 1280 + kb);
            mma_block(acc, af, bl);                 // hi * lo
            #pragma unroll
            for (int i = 0; i < 4; i++) ldsm4(af + i * 4, base + T_AL + aoff + i * 1280 + kb);
            mma_block(acc, af, bh);                 // lo * hi
        }
    }

    const int mb = m0 + wm * 64;
    const int nb = n0 + wn * 32;

    if (wsel < 2) {
        const float* bias = (wsel == 0) ? bq : bk;
        __half* Q = ((wsel == 0) ? g_qt16 : g_kt16) + (size_t)b * LL * CC;
        #pragma unroll
        for (int i = 0; i < 4; i++) {
            int r0 = mb + i * 16 + (lane >> 2);
            #pragma unroll
            for (int j = 0; j < 4; j++) {
                const float* c = acc + (i * 4 + j) * 4;
                int nn = nb + j * 8 + (lane & 3) * 2;
                float b0 = bias[nn], b1 = bias[nn + 1];
                *(__half2*)(Q + (size_t)r0 * CC + nn) =
                    __floats2half2_rn(c[0] + b0, c[1] + b1);
                *(__half2*)(Q + (size_t)(r0 + 8) * CC + nn) =
                    __floats2half2_rn(c[2] + b0, c[3] + b1);
            }
        }
    } else {
        __half* V = g_v16 + (size_t)b * CC * LL;
        #pragma unroll
        for (int i = 0; i < 4; i++) {
            int r0 = mb + i * 16 + (lane >> 2);
            float bi0 = bv[r0], bi8 = bv[r0 + 8];
            #pragma unroll
            for (int j = 0; j < 4; j++) {
                const float* c = acc + (i * 4 + j) * 4;
                int nn = nb + j * 8 + (lane & 3) * 2;
                *(__half2*)(V + (size_t)r0 * LL + nn) =
                    __floats2half2_rn(c[0] + bi0, c[1] + bi0);
                *(__half2*)(V + (size_t)(r0 + 8) * LL + nn) =
                    __floats2half2_rn(c[2] + bi8, c[3] + bi8);
            }
        }
    }
}

// ---------------------------------------------------------------------------
// scores: fp16 single-product. D = q_t * k_t^T; emits e^(s*scale) fp16 +
// per-CTA row partial sums into g_psum[b][l][16].
// ---------------------------------------------------------------------------
#define SMEM_DYN2 40960
#define STG2 20480

__global__ __launch_bounds__(256, 2) void scores_kernel()
{
    extern __shared__ char smem[];
    const uint32_t sb = smem_u32(smem);
    const int tid = threadIdx.x;
    const int lane = tid & 31, wid = tid >> 5;
    const int wm = wid & 1, wn = wid >> 1;

    const int b = blockIdx.y;
    const int m0 = (blockIdx.x >> 4) * 128;    // l
    const int n0 = (blockIdx.x & 15) * 128;    // m
    const __half* Q = g_qt16 + (size_t)b * LL * CC;
    const __half* K = g_kt16 + (size_t)b * LL * CC;
    const int NT = CC / 32;

    const uint32_t aoff = (uint32_t)((wm * 64 + (lane & 15)) * 80 + ((lane >> 4) * 16));
    const uint32_t boff = (uint32_t)((wn * 32 + (((lane >> 3) >> 1) * 8) + (lane & 7)) * 80
                                     + ((lane >> 3) & 1) * 16);

    float acc[64];
    #pragma unroll
    for (int i = 0; i < 64; i++) acc[i] = 0.f;

    cp_tile(sb + 0,     Q, m0, CC, 0, tid);
    cp_tile(sb + 10240, K, n0, CC, 0, tid);
    CP_COMMIT();

    for (int t = 0; t < NT; t++) {
        CP_WAIT0();
        __syncthreads();
        if (t + 1 < NT) {
            uint32_t nb2 = sb + ((t + 1) & 1) * STG2;
            int k0 = (t + 1) * 32;
            cp_tile(nb2 + 0,     Q, m0, CC, k0, tid);
            cp_tile(nb2 + 10240, K, n0, CC, k0, tid);
            CP_COMMIT();
        }
        const uint32_t base = sb + (t & 1) * STG2;
        #pragma unroll
        for (int ks = 0; ks < 2; ks++) {
            const uint32_t kb = ks * 32;
            uint32_t af[16], bf[8];
            #pragma unroll
            for (int i = 0; i < 4; i++) ldsm4(af + i * 4, base + aoff + i * 1280 + kb);
            #pragma unroll
            for (int jp = 0; jp < 2; jp++) ldsm4(bf + jp * 4, base + 10240 + boff + jp * 1280 + kb);
            mma_block_h(acc, af, bf);
        }
    }

    // epilogue: e = exp(s*scale), store + row partial sums
    const float scale = 0.044194173824159216f;   // 1/sqrt(512)
    const int mb = m0 + wm * 64;
    const int nb = n0 + wn * 32;
    __half* E = g_e16 + (size_t)b * LL * LL;

    __syncthreads();                              // tiles no longer needed
    float* ps = (float*)smem;                     // [128][4]

    #pragma unroll
    for (int i = 0; i < 4; i++) {
        int r0 = mb + i * 16 + (lane >> 2);
        float sA = 0.f, sB = 0.f;
        #pragma unroll
        for (int j = 0; j < 4; j++) {
            const float* c = acc + (i * 4 + j) * 4;
            int nn = nb + j * 8 + (lane & 3) * 2;
            float e0 = __expf(fminf(c[0] * scale, 11.f));
            float e1 = __expf(fminf(c[1] * scale, 11.f));
            float e2 = __expf(fminf(c[2] * scale, 11.f));
            float e3 = __expf(fminf(c[3] * scale, 11.f));
            *(__half2*)(E + (size_t)r0 * LL + nn)       = __floats2half2_rn(e0, e1);
            *(__half2*)(E + (size_t)(r0 + 8) * LL + nn) = __floats2half2_rn(e2, e3);
            sA += e0 + e1;
            sB += e2 + e3;
        }
        // reduce across the 4 lanes sharing this row (lane bits 0..1)
        #pragma unroll
        for (int o = 1; o <= 2; o <<= 1) {
            sA += __shfl_xor_sync(0xFFFFFFFFu, sA, o);
            sB += __shfl_xor_sync(0xFFFFFFFFu, sB, o);
        }
        if ((lane & 3) == 0) {
            int rloc = wm * 64 + i * 16 + (lane >> 2);
            ps[rloc * 4 + wn]       = sA;
            ps[(rloc + 8) * 4 + wn] = sB;
        }
    }
    __syncthreads();
    if (tid < 128) {
        float s = ps[tid * 4] + ps[tid * 4 + 1] + ps[tid * 4 + 2] + ps[tid * 4 + 3];
        g_psum[((size_t)b * LL + m0 + tid) * 16 + (n0 >> 7)] = s;
    }
}

// ---------------------------------------------------------------------------
// rowinv: 1 / sum of 16 partials per (b, l)
// ---------------------------------------------------------------------------
__global__ __launch_bounds__(256) void rowinv_kernel()
{
    int i = blockIdx.x * 256 + threadIdx.x;   // b*LL + l
    const float* p = &g_psum[(size_t)i * 16];
    float s = 0.f;
    #pragma unroll
    for (int k = 0; k < 16; k++) s += p[k];
    g_rinv[i] = 1.f / s;
}

// ---------------------------------------------------------------------------
// out = (V * E^T) * rinv, fp16 single-product
// ---------------------------------------------------------------------------
__global__ __launch_bounds__(256, 2) void out_kernel(float* __restrict__ outp)
{
    extern __shared__ char smem[];
    const uint32_t sb = smem_u32(smem);
    const int tid = threadIdx.x;
    const int lane = tid & 31, wid = tid >> 5;
    const int wm = wid & 1, wn = wid >> 1;

    const int b = blockIdx.y;
    const int m0 = (blockIdx.x & 3) * 128;     // c
    const int n0 = (blockIdx.x >> 2) * 128;    // l
    const __half* V = g_v16 + (size_t)b * CC * LL;
    const __half* E = g_e16 + (size_t)b * LL * LL;
    const int NT = LL / 32;

    const uint32_t aoff = (uint32_t)((wm * 64 + (lane & 15)) * 80 + ((lane >> 4) * 16));
    const uint32_t boff = (uint32_t)((wn * 32 + (((lane >> 3) >> 1) * 8) + (lane & 7)) * 80
                                     + ((lane >> 3) & 1) * 16);

    float acc[64];
    #pragma unroll
    for (int i = 0; i < 64; i++) acc[i] = 0.f;

    cp_tile(sb + 0,     V, m0, LL, 0, tid);
    cp_tile(sb + 10240, E, n0, LL, 0, tid);
    CP_COMMIT();

    for (int t = 0; t < NT; t++) {
        CP_WAIT0();
        __syncthreads();
        if (t + 1 < NT) {
            uint32_t nb2 = sb + ((t + 1) & 1) * STG2;
            int k0 = (t + 1) * 32;
            cp_tile(nb2 + 0,     V, m0, LL, k0, tid);
            cp_tile(nb2 + 10240, E, n0, LL, k0, tid);
            CP_COMMIT();
        }
        const uint32_t base = sb + (t & 1) * STG2;
        #pragma unroll
        for (int ks = 0; ks < 2; ks++) {
            const uint32_t kb = ks * 32;
            uint32_t af[16], bf[8];
            #pragma unroll
            for (int i = 0; i < 4; i++) ldsm4(af + i * 4, base + aoff + i * 1280 + kb);
            #pragma unroll
            for (int jp = 0; jp < 2; jp++) ldsm4(bf + jp * 4, base + 10240 + boff + jp * 1280 + kb);
            mma_block_h(acc, af, bf);
        }
    }

    const int mb = m0 + wm * 64;
    const int nb = n0 + wn * 32;
    const float* Rinv = g_rinv + (size_t)b * LL;
    float rv[8];
    #pragma unroll
    for (int j = 0; j < 4; j++) {
        int nn = nb + j * 8 + (lane & 3) * 2;
        float2 r2 = *(const float2*)&Rinv[nn];
        rv[j * 2] = r2.x; rv[j * 2 + 1] = r2.y;
    }

    float* O = outp + (size_t)b * CC * LL;
    #pragma unroll
    for (int i = 0; i < 4; i++) {
        int r0 = mb + i * 16 + (lane >> 2);
        #pragma unroll
        for (int j = 0; j < 4; j++) {
            const float* c = acc + (i * 4 + j) * 4;
            int nn = nb + j * 8 + (lane & 3) * 2;
            float2 v0 = {c[0] * rv[j * 2], c[1] * rv[j * 2 + 1]};
            float2 v1 = {c[2] * rv[j * 2], c[3] * rv[j * 2 + 1]};
            *(float2*)&O[(size_t)r0 * LL + nn]       = v0;
            *(float2*)&O[(size_t)(r0 + 8) * LL + nn] = v1;
        }
    }
}

// ---------------------------------------------------------------------------
extern "C" void kernel_launch(void* const* d_in, const int* in_sizes, int n_in,
                              void* d_out, int out_size)
{
    const float* x  = (const float*)d_in[0];
    const float* Wq = (const float*)d_in[1];
    const float* bq = (const float*)d_in[2];
    const float* Wk = (const float*)d_in[3];
    const float* bk = (const float*)d_in[4];
    const float* Wv = (const float*)d_in[5];
    const float* bv = (const float*)d_in[6];
    float* out = (float*)d_out;

    cudaFuncSetAttribute(proj_kernel,   cudaFuncAttributeMaxDynamicSharedMemorySize, SMEM_DYN);
    cudaFuncSetAttribute(scores_kernel, cudaFuncAttributeMaxDynamicSharedMemorySize, SMEM_DYN2);
    cudaFuncSetAttribute(out_kernel,    cudaFuncAttributeMaxDynamicSharedMemorySize, SMEM_DYN2);

    conv_w<<<3 * CC * CC / 256, 256>>>(Wq, Wk, Wv);
    conv_x<<<dim3(LL / 32, CC / 32, BB), 256>>>(x);

    proj_kernel<<<dim3(64, 3 * BB), 256, SMEM_DYN>>>(bq, bk, bv);
    scores_kernel<<<dim3(256, BB), 256, SMEM_DYN2>>>();
    rowinv_kernel<<<BB * LL / 256, 256>>>();
    out_kernel<<<dim3(64, BB), 256, SMEM_DYN2>>>(out);
}

// round 7
// speedup vs baseline: 6.8883x; 1.3430x over previous
#include <cuda_runtime.h>
#include <cuda_fp16.h>
#include <cstdint>

#define BB 8
#define CC 512
#define LL 2048

// ---------------------------------------------------------------------------
// Device scratch (all fp16 operands)
// ---------------------------------------------------------------------------
__device__ __half g_xt16[(size_t)BB * LL * CC];    // x^T [b][l][c]
__device__ __half g_w16[3 * CC * CC];              // W   [w][c_out][c_in]
__device__ __half g_qt16[(size_t)BB * LL * CC];    // q^T [b][l][c]
__device__ __half g_kt16[(size_t)BB * LL * CC];    // k^T [b][m][c]
__device__ __half g_v16[(size_t)BB * CC * LL];     // v   [b][c][m]
__device__ __half g_e16[(size_t)BB * LL * LL];     // e^s [b][l][m]
__device__ float  g_psum[(size_t)BB * LL * 16];    // partial row sums
__device__ float  g_rinv[(size_t)BB * LL];         // 1 / row sum

// ---------------------------------------------------------------------------
// Helpers (baseline PTX only)
// ---------------------------------------------------------------------------
__device__ __forceinline__ uint32_t smem_u32(const void* p) {
    uint32_t a;
    asm("{ .reg .u64 t; cvta.to.shared.u64 t, %1; cvt.u32.u64 %0, t; }"
        : "=r"(a) : "l"(p));
    return a;
}

__device__ __forceinline__ void ldsm4(uint32_t* r, uint32_t addr) {
    asm volatile("ldmatrix.sync.aligned.m8n8.x4.shared.b16 {%0,%1,%2,%3}, [%4];"
                 : "=r"(r[0]), "=r"(r[1]), "=r"(r[2]), "=r"(r[3]) : "r"(addr));
}

__device__ __forceinline__ void mma16816h(float* c, const uint32_t* a, const uint32_t* b) {
    asm volatile(
        "mma.sync.aligned.m16n8k16.row.col.f32.f16.f16.f32 "
        "{%0,%1,%2,%3}, {%4,%5,%6,%7}, {%8,%9}, {%0,%1,%2,%3};"
        : "+f"(c[0]), "+f"(c[1]), "+f"(c[2]), "+f"(c[3])
        : "r"(a[0]), "r"(a[1]), "r"(a[2]), "r"(a[3]), "r"(b[0]), "r"(b[1]));
}

#define CP16(dst, src) \
    asm volatile("cp.async.cg.shared.global [%0], [%1], 16;" :: "r"(dst), "l"(src))
#define CP_COMMIT() asm volatile("cp.async.commit_group;" ::: "memory")
#define CP_WAIT0()  asm volatile("cp.async.wait_group 0;" ::: "memory")

// ---------------------------------------------------------------------------
// Conversion kernels
// ---------------------------------------------------------------------------
__global__ __launch_bounds__(256) void conv_w(
    const float* __restrict__ Wq, const float* __restrict__ Wk,
    const float* __restrict__ Wv)
{
    int idx = blockIdx.x * 256 + threadIdx.x;
    int wsel = idx >> 18;
    int off = idx & 262143;
    const float* W = (wsel == 0) ? Wq : (wsel == 1) ? Wk : Wv;
    g_w16[idx] = __float2half(W[off]);
}

__global__ __launch_bounds__(256) void conv_x(const float* __restrict__ x)
{
    __shared__ float ts[32][33];
    int b = blockIdx.z, c0 = blockIdx.y * 32, l0 = blockIdx.x * 32;
    int lane = threadIdx.x & 31, wrp = threadIdx.x >> 5;
    const float* X = x + ((size_t)b * CC + c0) * LL + l0;
    #pragma unroll
    for (int ii = 0; ii < 4; ii++)
        ts[wrp + 8 * ii][lane] = X[(size_t)(wrp + 8 * ii) * LL + lane];
    __syncthreads();
    size_t base = ((size_t)b * LL + l0) * CC + c0;
    #pragma unroll
    for (int ii = 0; ii < 4; ii++) {
        int lr = wrp + 8 * ii;
        g_xt16[base + (size_t)lr * CC + lane] = __float2half(ts[lane][lr]);
    }
}

// ---------------------------------------------------------------------------
// Common tile copier: 128 rows x 32 fp16 (64B) per tile, 80B pitch
// ---------------------------------------------------------------------------
__device__ __forceinline__ void cp_tile(uint32_t dst_base,
    const __half* __restrict__ g, int row0, int ld, int k0, int tid)
{
    #pragma unroll
    for (int i = 0; i < 2; i++) {
        int idx = i * 256 + tid;
        int r = idx >> 2, u = idx & 3;
        uint32_t dst = dst_base + (uint32_t)r * 80u + (uint32_t)u * 16u;
        const __half* src = g + (size_t)(row0 + r) * ld + k0 + u * 8;
        CP16(dst, src);
    }
}

__device__ __forceinline__ void mma_block_h(float* acc, const uint32_t* af, const uint32_t* bf)
{
    #pragma unroll
    for (int i = 0; i < 4; i++)
        #pragma unroll
        for (int j = 0; j < 4; j++)
            mma16816h(acc + (i * 4 + j) * 4, af + i * 4, bf + (j >> 1) * 4 + (j & 1) * 2);
}

// ---------------------------------------------------------------------------
// Shared GEMM mainloop: CTA 128x128, 8 warps 64x32, BK=32, 2 stages.
// Stage: A@0, B@10240; stage stride 20480; smem total 40960.
// ---------------------------------------------------------------------------
#define SMEM_DYN 40960
#define STG 20480

__device__ __forceinline__ void gemm_mainloop(
    uint32_t sb, const __half* A, const __half* B, int m0, int n0,
    int lda, int ldb, int NT, int tid, uint32_t aoff, uint32_t boff, float* acc)
{
    cp_tile(sb + 0,     A, m0, lda, 0, tid);
    cp_tile(sb + 10240, B, n0, ldb, 0, tid);
    CP_COMMIT();

    for (int t = 0; t < NT; t++) {
        CP_WAIT0();
        __syncthreads();
        if (t + 1 < NT) {
            uint32_t nb = sb + ((t + 1) & 1) * STG;
            int k0 = (t + 1) * 32;
            cp_tile(nb + 0,     A, m0, lda, k0, tid);
            cp_tile(nb + 10240, B, n0, ldb, k0, tid);
            CP_COMMIT();
        }
        const uint32_t base = sb + (t & 1) * STG;
        #pragma unroll
        for (int ks = 0; ks < 2; ks++) {
            const uint32_t kb = ks * 32;
            uint32_t af[16], bf[8];
            #pragma unroll
            for (int i = 0; i < 4; i++) ldsm4(af + i * 4, base + aoff + i * 1280 + kb);
            #pragma unroll
            for (int jp = 0; jp < 2; jp++) ldsm4(bf + jp * 4, base + 10240 + boff + jp * 1280 + kb);
            mma_block_h(acc, af, bf);
        }
    }
}

#define WARP_GEOM \
    const int tid = threadIdx.x; \
    const int lane = tid & 31, wid = tid >> 5; \
    const int wm = wid & 1, wn = wid >> 1; \
    const uint32_t aoff = (uint32_t)((wm * 64 + (lane & 15)) * 80 + ((lane >> 4) * 16)); \
    const uint32_t boff = (uint32_t)((wn * 32 + (((lane >> 3) >> 1) * 8) + (lane & 7)) * 80 \
                                     + ((lane >> 3) & 1) * 16);

// ---------------------------------------------------------------------------
// proj: fp16 GEMM. wsel<2: D[l][c_out]=x_t*W^T -> q/k ; wsel=2: D[c][l] -> v
// ---------------------------------------------------------------------------
__global__ __launch_bounds__(256, 2) void proj_kernel(
    const float* __restrict__ bq, const float* __restrict__ bk,
    const float* __restrict__ bv)
{
    extern __shared__ char smem[];
    const uint32_t sb = smem_u32(smem);
    WARP_GEOM

    int id = blockIdx.x;
    int b = blockIdx.y / 3, wsel = blockIdx.y % 3;
    const __half *A, *B;
    int m0, n0;
    if (wsel < 2) {
        m0 = (id >> 2) * 128; n0 = (id & 3) * 128;           // m=l, n=c_out
        A = g_xt16 + (size_t)b * LL * CC;
        B = g_w16 + (size_t)wsel * CC * CC;
    } else {
        m0 = (id & 3) * 128; n0 = (id >> 2) * 128;           // m=c_out, n=l
        A = g_w16 + (size_t)2 * CC * CC;
        B = g_xt16 + (size_t)b * LL * CC;
    }

    float acc[64];
    #pragma unroll
    for (int i = 0; i < 64; i++) acc[i] = 0.f;

    gemm_mainloop(sb, A, B, m0, n0, CC, CC, CC / 32, tid, aoff, boff, acc);

    const int mb = m0 + wm * 64;
    const int nb = n0 + wn * 32;

    if (wsel < 2) {
        const float* bias = (wsel == 0) ? bq : bk;
        __half* Q = ((wsel == 0) ? g_qt16 : g_kt16) + (size_t)b * LL * CC;
        #pragma unroll
        for (int i = 0; i < 4; i++) {
            int r0 = mb + i * 16 + (lane >> 2);
            #pragma unroll
            for (int j = 0; j < 4; j++) {
                const float* c = acc + (i * 4 + j) * 4;
                int nn = nb + j * 8 + (lane & 3) * 2;
                float b0 = bias[nn], b1 = bias[nn + 1];
                *(__half2*)(Q + (size_t)r0 * CC + nn) =
                    __floats2half2_rn(c[0] + b0, c[1] + b1);
                *(__half2*)(Q + (size_t)(r0 + 8) * CC + nn) =
                    __floats2half2_rn(c[2] + b0, c[3] + b1);
            }
        }
    } else {
        __half* V = g_v16 + (size_t)b * CC * LL;
        #pragma unroll
        for (int i = 0; i < 4; i++) {
            int r0 = mb + i * 16 + (lane >> 2);
            float bi0 = bv[r0], bi8 = bv[r0 + 8];
            #pragma unroll
            for (int j = 0; j < 4; j++) {
                const float* c = acc + (i * 4 + j) * 4;
                int nn = nb + j * 8 + (lane & 3) * 2;
                *(__half2*)(V + (size_t)r0 * LL + nn) =
                    __floats2half2_rn(c[0] + bi0, c[1] + bi0);
                *(__half2*)(V + (size_t)(r0 + 8) * LL + nn) =
                    __floats2half2_rn(c[2] + bi8, c[3] + bi8);
            }
        }
    }
}

// ---------------------------------------------------------------------------
// scores: D = q_t * k_t^T; emits e^(s*scale) fp16 + row partial sums
// ---------------------------------------------------------------------------
__global__ __launch_bounds__(256, 2) void scores_kernel()
{
    extern __shared__ char smem[];
    const uint32_t sb = smem_u32(smem);
    WARP_GEOM

    const int b = blockIdx.y;
    const int m0 = (blockIdx.x >> 4) * 128;    // l
    const int n0 = (blockIdx.x & 15) * 128;    // m
    const __half* Q = g_qt16 + (size_t)b * LL * CC;
    const __half* K = g_kt16 + (size_t)b * LL * CC;

    float acc[64];
    #pragma unroll
    for (int i = 0; i < 64; i++) acc[i] = 0.f;

    gemm_mainloop(sb, Q, K, m0, n0, CC, CC, CC / 32, tid, aoff, boff, acc);

    const float scale = 0.044194173824159216f;   // 1/sqrt(512)
    const int mb = m0 + wm * 64;
    const int nb = n0 + wn * 32;
    __half* E = g_e16 + (size_t)b * LL * LL;

    __syncthreads();
    float* ps = (float*)smem;                     // [128][4]

    #pragma unroll
    for (int i = 0; i < 4; i++) {
        int r0 = mb + i * 16 + (lane >> 2);
        float sA = 0.f, sB = 0.f;
        #pragma unroll
        for (int j = 0; j < 4; j++) {
            const float* c = acc + (i * 4 + j) * 4;
            int nn = nb + j * 8 + (lane & 3) * 2;
            float e0 = __expf(fminf(c[0] * scale, 11.f));
            float e1 = __expf(fminf(c[1] * scale, 11.f));
            float e2 = __expf(fminf(c[2] * scale, 11.f));
            float e3 = __expf(fminf(c[3] * scale, 11.f));
            *(__half2*)(E + (size_t)r0 * LL + nn)       = __floats2half2_rn(e0, e1);
            *(__half2*)(E + (size_t)(r0 + 8) * LL + nn) = __floats2half2_rn(e2, e3);
            sA += e0 + e1;
            sB += e2 + e3;
        }
        #pragma unroll
        for (int o = 1; o <= 2; o <<= 1) {
            sA += __shfl_xor_sync(0xFFFFFFFFu, sA, o);
            sB += __shfl_xor_sync(0xFFFFFFFFu, sB, o);
        }
        if ((lane & 3) == 0) {
            int rloc = wm * 64 + i * 16 + (lane >> 2);
            ps[rloc * 4 + wn]       = sA;
            ps[(rloc + 8) * 4 + wn] = sB;
        }
    }
    __syncthreads();
    if (tid < 128) {
        float s = ps[tid * 4] + ps[tid * 4 + 1] + ps[tid * 4 + 2] + ps[tid * 4 + 3];
        g_psum[((size_t)b * LL + m0 + tid) * 16 + (n0 >> 7)] = s;
    }
}

// ---------------------------------------------------------------------------
// rowinv: 1 / sum of 16 partials per (b, l)
// ---------------------------------------------------------------------------
__global__ __launch_bounds__(256) void rowinv_kernel()
{
    int i = blockIdx.x * 256 + threadIdx.x;
    const float* p = &g_psum[(size_t)i * 16];
    float s = 0.f;
    #pragma unroll
    for (int k = 0; k < 16; k++) s += p[k];
    g_rinv[i] = 1.f / s;
}

// ---------------------------------------------------------------------------
// out = (V * E^T) * rinv
// ---------------------------------------------------------------------------
__global__ __launch_bounds__(256, 2) void out_kernel(float* __restrict__ outp)
{
    extern __shared__ char smem[];
    const uint32_t sb = smem_u32(smem);
    WARP_GEOM

    const int b = blockIdx.y;
    const int m0 = (blockIdx.x & 3) * 128;     // c
    const int n0 = (blockIdx.x >> 2) * 128;    // l
    const __half* V = g_v16 + (size_t)b * CC * LL;
    const __half* E = g_e16 + (size_t)b * LL * LL;

    float acc[64];
    #pragma unroll
    for (int i = 0; i < 64; i++) acc[i] = 0.f;

    gemm_mainloop(sb, V, E, m0, n0, LL, LL, LL / 32, tid, aoff, boff, acc);

    const int mb = m0 + wm * 64;
    const int nb = n0 + wn * 32;
    const float* Rinv = g_rinv + (size_t)b * LL;
    float rv[8];
    #pragma unroll
    for (int j = 0; j < 4; j++) {
        int nn = nb + j * 8 + (lane & 3) * 2;
        float2 r2 = *(const float2*)&Rinv[nn];
        rv[j * 2] = r2.x; rv[j * 2 + 1] = r2.y;
    }

    float* O = outp + (size_t)b * CC * LL;
    #pragma unroll
    for (int i = 0; i < 4; i++) {
        int r0 = mb + i * 16 + (lane >> 2);
        #pragma unroll
        for (int j = 0; j < 4; j++) {
            const float* c = acc + (i * 4 + j) * 4;
            int nn = nb + j * 8 + (lane & 3) * 2;
            float2 v0 = {c[0] * rv[j * 2], c[1] * rv[j * 2 + 1]};
            float2 v1 = {c[2] * rv[j * 2], c[3] * rv[j * 2 + 1]};
            *(float2*)&O[(size_t)r0 * LL + nn]       = v0;
            *(float2*)&O[(size_t)(r0 + 8) * LL + nn] = v1;
        }
    }
}

// ---------------------------------------------------------------------------
extern "C" void kernel_launch(void* const* d_in, const int* in_sizes, int n_in,
                              void* d_out, int out_size)
{
    const float* x  = (const float*)d_in[0];
    const float* Wq = (const float*)d_in[1];
    const float* bq = (const float*)d_in[2];
    const float* Wk = (const float*)d_in[3];
    const float* bk = (const float*)d_in[4];
    const float* Wv = (const float*)d_in[5];
    const float* bv = (const float*)d_in[6];
    float* out = (float*)d_out;

    cudaFuncSetAttribute(proj_kernel,   cudaFuncAttributeMaxDynamicSharedMemorySize, SMEM_DYN);
    cudaFuncSetAttribute(scores_kernel, cudaFuncAttributeMaxDynamicSharedMemorySize, SMEM_DYN);
    cudaFuncSetAttribute(out_kernel,    cudaFuncAttributeMaxDynamicSharedMemorySize, SMEM_DYN);

    conv_w<<<3 * CC * CC / 256, 256>>>(Wq, Wk, Wv);
    conv_x<<<dim3(LL / 32, CC / 32, BB), 256>>>(x);

    proj_kernel<<<dim3(64, 3 * BB), 256, SMEM_DYN>>>(bq, bk, bv);
    scores_kernel<<<dim3(256, BB), 256, SMEM_DYN>>>();
    rowinv_kernel<<<BB * LL / 256, 256>>>();
    out_kernel<<<dim3(64, BB), 256, SMEM_DYN>>>(out);
}

// round 8
// speedup vs baseline: 7.7622x; 1.1269x over previous
#include <cuda_runtime.h>
#include <cuda_fp16.h>
#include <cstdint>

#define BB 8
#define CC 512
#define LL 2048

// ---------------------------------------------------------------------------
// Device scratch (all fp16 operands)
// ---------------------------------------------------------------------------
__device__ __half g_xt16[(size_t)BB * LL * CC];    // x^T [b][l][c]
__device__ __half g_w16[3 * CC * CC];              // W   [w][c_out][c_in]
__device__ __half g_qt16[(size_t)BB * LL * CC];    // q^T [b][l][c]
__device__ __half g_kt16[(size_t)BB * LL * CC];    // k^T [b][m][c]
__device__ __half g_v16[(size_t)BB * CC * LL];     // v   [b][c][m]
__device__ __half g_e16[(size_t)BB * LL * LL];     // e^s [b][l][m]
__device__ float  g_psum[(size_t)BB * LL * 16];    // partial row sums
__device__ float  g_rinv[(size_t)BB * LL];         // 1 / row sum

// ---------------------------------------------------------------------------
// Helpers (baseline PTX only)
// ---------------------------------------------------------------------------
__device__ __forceinline__ uint32_t smem_u32(const void* p) {
    uint32_t a;
    asm("{ .reg .u64 t; cvta.to.shared.u64 t, %1; cvt.u32.u64 %0, t; }"
        : "=r"(a) : "l"(p));
    return a;
}

__device__ __forceinline__ void ldsm4(uint32_t* r, uint32_t addr) {
    asm volatile("ldmatrix.sync.aligned.m8n8.x4.shared.b16 {%0,%1,%2,%3}, [%4];"
                 : "=r"(r[0]), "=r"(r[1]), "=r"(r[2]), "=r"(r[3]) : "r"(addr));
}

__device__ __forceinline__ void mma16816h(float* c, const uint32_t* a, const uint32_t* b) {
    asm volatile(
        "mma.sync.aligned.m16n8k16.row.col.f32.f16.f16.f32 "
        "{%0,%1,%2,%3}, {%4,%5,%6,%7}, {%8,%9}, {%0,%1,%2,%3};"
        : "+f"(c[0]), "+f"(c[1]), "+f"(c[2]), "+f"(c[3])
        : "r"(a[0]), "r"(a[1]), "r"(a[2]), "r"(a[3]), "r"(b[0]), "r"(b[1]));
}

#define CP16(dst, src) \
    asm volatile("cp.async.cg.shared.global [%0], [%1], 16;" :: "r"(dst), "l"(src))
#define CP_COMMIT() asm volatile("cp.async.commit_group;" ::: "memory")
#define CP_WAIT1()  asm volatile("cp.async.wait_group 1;" ::: "memory")

// ---------------------------------------------------------------------------
// Conversion kernels
// ---------------------------------------------------------------------------
__global__ __launch_bounds__(256) void conv_w(
    const float* __restrict__ Wq, const float* __restrict__ Wk,
    const float* __restrict__ Wv)
{
    int idx = blockIdx.x * 256 + threadIdx.x;
    int wsel = idx >> 18;
    int off = idx & 262143;
    const float* W = (wsel == 0) ? Wq : (wsel == 1) ? Wk : Wv;
    g_w16[idx] = __float2half(W[off]);
}

__global__ __launch_bounds__(256) void conv_x(const float* __restrict__ x)
{
    __shared__ float ts[32][33];
    int b = blockIdx.z, c0 = blockIdx.y * 32, l0 = blockIdx.x * 32;
    int lane = threadIdx.x & 31, wrp = threadIdx.x >> 5;
    const float* X = x + ((size_t)b * CC + c0) * LL + l0;
    #pragma unroll
    for (int ii = 0; ii < 4; ii++)
        ts[wrp + 8 * ii][lane] = X[(size_t)(wrp + 8 * ii) * LL + lane];
    __syncthreads();
    size_t base = ((size_t)b * LL + l0) * CC + c0;
    #pragma unroll
    for (int ii = 0; ii < 4; ii++) {
        int lr = wrp + 8 * ii;
        g_xt16[base + (size_t)lr * CC + lane] = __float2half(ts[lane][lr]);
    }
}

// ---------------------------------------------------------------------------
// Common tile copier: 128 rows x 32 fp16 (64B) per tile, 80B pitch
// ---------------------------------------------------------------------------
__device__ __forceinline__ void cp_tile(uint32_t dst_base,
    const __half* __restrict__ g, int row0, int ld, int k0, int tid)
{
    #pragma unroll
    for (int i = 0; i < 2; i++) {
        int idx = i * 256 + tid;
        int r = idx >> 2, u = idx & 3;
        uint32_t dst = dst_base + (uint32_t)r * 80u + (uint32_t)u * 16u;
        const __half* src = g + (size_t)(row0 + r) * ld + k0 + u * 8;
        CP16(dst, src);
    }
}

__device__ __forceinline__ void mma_block_h(float* acc, const uint32_t* af, const uint32_t* bf)
{
    #pragma unroll
    for (int i = 0; i < 4; i++)
        #pragma unroll
        for (int j = 0; j < 4; j++)
            mma16816h(acc + (i * 4 + j) * 4, af + i * 4, bf + (j >> 1) * 4 + (j & 1) * 2);
}

// ---------------------------------------------------------------------------
// Shared GEMM mainloop: CTA 128x128, 8 warps 64x32, BK=32, 3-stage cp.async
// pipeline (wait_group 1) + register fragment double-buffering.
// Stage: A@0, B@10240; stage stride 20480; smem total 61440.
// ---------------------------------------------------------------------------
#define SMEM_DYN 61440
#define STG 20480

__device__ __forceinline__ void gemm_mainloop(
    uint32_t sb, const __half* A, const __half* B, int m0, int n0,
    int lda, int ldb, int NT, int tid, uint32_t aoff, uint32_t boff, float* acc)
{
    // prologue: stages 0 and 1 in flight
    cp_tile(sb + 0,     A, m0, lda, 0, tid);
    cp_tile(sb + 10240, B, n0, ldb, 0, tid);
    CP_COMMIT();
    if (NT > 1) {
        cp_tile(sb + STG,         A, m0, lda, 32, tid);
        cp_tile(sb + STG + 10240, B, n0, ldb, 32, tid);
    }
    CP_COMMIT();
    CP_WAIT1();                 // stage 0 resident
    __syncthreads();

    uint32_t af[2][16], bf[2][8];
    #pragma unroll
    for (int i = 0; i < 4; i++)  ldsm4(af[0] + i * 4,  sb + aoff + i * 1280);
    #pragma unroll
    for (int jp = 0; jp < 2; jp++) ldsm4(bf[0] + jp * 4, sb + 10240 + boff + jp * 1280);

    for (int t = 0; t < NT; t++) {
        const uint32_t base = sb + (uint32_t)(t % 3) * STG;
        if (t + 2 < NT) {
            uint32_t nb = sb + (uint32_t)((t + 2) % 3) * STG;
            int k0 = (t + 2) * 32;
            cp_tile(nb + 0,     A, m0, lda, k0, tid);
            cp_tile(nb + 10240, B, n0, ldb, k0, tid);
        }
        CP_COMMIT();            // one group per iter (possibly empty)

        // phase ks=0: prefetch ks=1 frags, then MMA on ks=0 frags
        #pragma unroll
        for (int i = 0; i < 4; i++)  ldsm4(af[1] + i * 4,  base + aoff + i * 1280 + 32);
        #pragma unroll
        for (int jp = 0; jp < 2; jp++) ldsm4(bf[1] + jp * 4, base + 10240 + boff + jp * 1280 + 32);
        mma_block_h(acc, af[0], bf[0]);

        // phase ks=1: wait next stage, prefetch next tile's ks=0 frags, MMA ks=1
        if (t + 1 < NT) {
            CP_WAIT1();         // stage t+1 resident (<=1 group outstanding)
            __syncthreads();
            const uint32_t nbase = sb + (uint32_t)((t + 1) % 3) * STG;
            #pragma unroll
            for (int i = 0; i < 4; i++)  ldsm4(af[0] + i * 4,  nbase + aoff + i * 1280);
            #pragma unroll
            for (int jp = 0; jp < 2; jp++) ldsm4(bf[0] + jp * 4, nbase + 10240 + boff + jp * 1280);
        }
        mma_block_h(acc, af[1], bf[1]);
    }
}

#define WARP_GEOM \
    const int tid = threadIdx.x; \
    const int lane = tid & 31, wid = tid >> 5; \
    const int wm = wid & 1, wn = wid >> 1; \
    const uint32_t aoff = (uint32_t)((wm * 64 + (lane & 15)) * 80 + ((lane >> 4) * 16)); \
    const uint32_t boff = (uint32_t)((wn * 32 + (((lane >> 3) >> 1) * 8) + (lane & 7)) * 80 \
                                     + ((lane >> 3) & 1) * 16);

// ---------------------------------------------------------------------------
// proj: fp16 GEMM. wsel<2: D[l][c_out]=x_t*W^T -> q/k ; wsel=2: D[c][l] -> v
// ---------------------------------------------------------------------------
__global__ __launch_bounds__(256, 2) void proj_kernel(
    const float* __restrict__ bq, const float* __restrict__ bk,
    const float* __restrict__ bv)
{
    extern __shared__ char smem[];
    const uint32_t sb = smem_u32(smem);
    WARP_GEOM

    int id = blockIdx.x;
    int b = blockIdx.y / 3, wsel = blockIdx.y % 3;
    const __half *A, *B;
    int m0, n0;
    if (wsel < 2) {
        m0 = (id >> 2) * 128; n0 = (id & 3) * 128;           // m=l, n=c_out
        A = g_xt16 + (size_t)b * LL * CC;
        B = g_w16 + (size_t)wsel * CC * CC;
    } else {
        m0 = (id & 3) * 128; n0 = (id >> 2) * 128;           // m=c_out, n=l
        A = g_w16 + (size_t)2 * CC * CC;
        B = g_xt16 + (size_t)b * LL * CC;
    }

    float acc[64];
    #pragma unroll
    for (int i = 0; i < 64; i++) acc[i] = 0.f;

    gemm_mainloop(sb, A, B, m0, n0, CC, CC, CC / 32, tid, aoff, boff, acc);

    const int mb = m0 + wm * 64;
    const int nb = n0 + wn * 32;

    if (wsel < 2) {
        const float* bias = (wsel == 0) ? bq : bk;
        __half* Q = ((wsel == 0) ? g_qt16 : g_kt16) + (size_t)b * LL * CC;
        #pragma unroll
        for (int i = 0; i < 4; i++) {
            int r0 = mb + i * 16 + (lane >> 2);
            #pragma unroll
            for (int j = 0; j < 4; j++) {
                const float* c = acc + (i * 4 + j) * 4;
                int nn = nb + j * 8 + (lane & 3) * 2;
                float b0 = bias[nn], b1 = bias[nn + 1];
                *(__half2*)(Q + (size_t)r0 * CC + nn) =
                    __floats2half2_rn(c[0] + b0, c[1] + b1);
                *(__half2*)(Q + (size_t)(r0 + 8) * CC + nn) =
                    __floats2half2_rn(c[2] + b0, c[3] + b1);
            }
        }
    } else {
        __half* V = g_v16 + (size_t)b * CC * LL;
        #pragma unroll
        for (int i = 0; i < 4; i++) {
            int r0 = mb + i * 16 + (lane >> 2);
            float bi0 = bv[r0], bi8 = bv[r0 + 8];
            #pragma unroll
            for (int j = 0; j < 4; j++) {
                const float* c = acc + (i * 4 + j) * 4;
                int nn = nb + j * 8 + (lane & 3) * 2;
                *(__half2*)(V + (size_t)r0 * LL + nn) =
                    __floats2half2_rn(c[0] + bi0, c[1] + bi0);
                *(__half2*)(V + (size_t)(r0 + 8) * LL + nn) =
                    __floats2half2_rn(c[2] + bi8, c[3] + bi8);
            }
        }
    }
}

// ---------------------------------------------------------------------------
// scores: D = q_t * k_t^T; emits e^(s*scale) fp16 + row partial sums
// ---------------------------------------------------------------------------
__global__ __launch_bounds__(256, 2) void scores_kernel()
{
    extern __shared__ char smem[];
    const uint32_t sb = smem_u32(smem);
    WARP_GEOM

    const int b = blockIdx.y;
    const int m0 = (blockIdx.x >> 4) * 128;    // l
    const int n0 = (blockIdx.x & 15) * 128;    // m
    const __half* Q = g_qt16 + (size_t)b * LL * CC;
    const __half* K = g_kt16 + (size_t)b * LL * CC;

    float acc[64];
    #pragma unroll
    for (int i = 0; i < 64; i++) acc[i] = 0.f;

    gemm_mainloop(sb, Q, K, m0, n0, CC, CC, CC / 32, tid, aoff, boff, acc);

    const float scale = 0.044194173824159216f;   // 1/sqrt(512)
    const int mb = m0 + wm * 64;
    const int nb = n0 + wn * 32;
    __half* E = g_e16 + (size_t)b * LL * LL;

    __syncthreads();
    float* ps = (float*)smem;                     // [128][4]

    #pragma unroll
    for (int i = 0; i < 4; i++) {
        int r0 = mb + i * 16 + (lane >> 2);
        float sA = 0.f, sB = 0.f;
        #pragma unroll
        for (int j = 0; j < 4; j++) {
            const float* c = acc + (i * 4 + j) * 4;
            int nn = nb + j * 8 + (lane & 3) * 2;
            float e0 = __expf(fminf(c[0] * scale, 11.f));
            float e1 = __expf(fminf(c[1] * scale, 11.f));
            float e2 = __expf(fminf(c[2] * scale, 11.f));
            float e3 = __expf(fminf(c[3] * scale, 11.f));
            *(__half2*)(E + (size_t)r0 * LL + nn)       = __floats2half2_rn(e0, e1);
            *(__half2*)(E + (size_t)(r0 + 8) * LL + nn) = __floats2half2_rn(e2, e3);
            sA += e0 + e1;
            sB += e2 + e3;
        }
        #pragma unroll
        for (int o = 1; o <= 2; o <<= 1) {
            sA += __shfl_xor_sync(0xFFFFFFFFu, sA, o);
            sB += __shfl_xor_sync(0xFFFFFFFFu, sB, o);
        }
        if ((lane & 3) == 0) {
            int rloc = wm * 64 + i * 16 + (lane >> 2);
            ps[rloc * 4 + wn]       = sA;
            ps[(rloc + 8) * 4 + wn] = sB;
        }
    }
    __syncthreads();
    if (tid < 128) {
        float s = ps[tid * 4] + ps[tid * 4 + 1] + ps[tid * 4 + 2] + ps[tid * 4 + 3];
        g_psum[((size_t)b * LL + m0 + tid) * 16 + (n0 >> 7)] = s;
    }
}

// ---------------------------------------------------------------------------
// rowinv: 1 / sum of 16 partials per (b, l)
// ---------------------------------------------------------------------------
__global__ __launch_bounds__(256) void rowinv_kernel()
{
    int i = blockIdx.x * 256 + threadIdx.x;
    const float* p = &g_psum[(size_t)i * 16];
    float s = 0.f;
    #pragma unroll
    for (int k = 0; k < 16; k++) s += p[k];
    g_rinv[i] = 1.f / s;
}

// ---------------------------------------------------------------------------
// out = (V * E^T) * rinv
// ---------------------------------------------------------------------------
__global__ __launch_bounds__(256, 2) void out_kernel(float* __restrict__ outp)
{
    extern __shared__ char smem[];
    const uint32_t sb = smem_u32(smem);
    WARP_GEOM

    const int b = blockIdx.y;
    const int m0 = (blockIdx.x & 3) * 128;     // c
    const int n0 = (blockIdx.x >> 2) * 128;    // l
    const __half* V = g_v16 + (size_t)b * CC * LL;
    const __half* E = g_e16 + (size_t)b * LL * LL;

    float acc[64];
    #pragma unroll
    for (int i = 0; i < 64; i++) acc[i] = 0.f;

    gemm_mainloop(sb, V, E, m0, n0, LL, LL, LL / 32, tid, aoff, boff, acc);

    const int mb = m0 + wm * 64;
    const int nb = n0 + wn * 32;
    const float* Rinv = g_rinv + (size_t)b * LL;
    float rv[8];
    #pragma unroll
    for (int j = 0; j < 4; j++) {
        int nn = nb + j * 8 + (lane & 3) * 2;
        float2 r2 = *(const float2*)&Rinv[nn];
        rv[j * 2] = r2.x; rv[j * 2 + 1] = r2.y;
    }

    float* O = outp + (size_t)b * CC * LL;
    #pragma unroll
    for (int i = 0; i < 4; i++) {
        int r0 = mb + i * 16 + (lane >> 2);
        #pragma unroll
        for (int j = 0; j < 4; j++) {
            const float* c = acc + (i * 4 + j) * 4;
            int nn = nb + j * 8 + (lane & 3) * 2;
            float2 v0 = {c[0] * rv[j * 2], c[1] * rv[j * 2 + 1]};
            float2 v1 = {c[2] * rv[j * 2], c[3] * rv[j * 2 + 1]};
            *(float2*)&O[(size_t)r0 * LL + nn]       = v0;
            *(float2*)&O[(size_t)(r0 + 8) * LL + nn] = v1;
        }
    }
}

// ---------------------------------------------------------------------------
extern "C" void kernel_launch(void* const* d_in, const int* in_sizes, int n_in,
                              void* d_out, int out_size)
{
    const float* x  = (const float*)d_in[0];
    const float* Wq = (const float*)d_in[1];
    const float* bq = (const float*)d_in[2];
    const float* Wk = (const float*)d_in[3];
    const float* bk = (const float*)d_in[4];
    const float* Wv = (const float*)d_in[5];
    const float* bv = (const float*)d_in[6];
    float* out = (float*)d_out;

    cudaFuncSetAttribute(proj_kernel,   cudaFuncAttributeMaxDynamicSharedMemorySize, SMEM_DYN);
    cudaFuncSetAttribute(scores_kernel, cudaFuncAttributeMaxDynamicSharedMemorySize, SMEM_DYN);
    cudaFuncSetAttribute(out_kernel,    cudaFuncAttributeMaxDynamicSharedMemorySize, SMEM_DYN);

    conv_w<<<3 * CC * CC / 256, 256>>>(Wq, Wk, Wv);
    conv_x<<<dim3(LL / 32, CC / 32, BB), 256>>>(x);

    proj_kernel<<<dim3(64, 3 * BB), 256, SMEM_DYN>>>(bq, bk, bv);
    scores_kernel<<<dim3(256, BB), 256, SMEM_DYN>>>();
    rowinv_kernel<<<BB * LL / 256, 256>>>();
    out_kernel<<<dim3(64, BB), 256, SMEM_DYN>>>(out);
}

// round 9
// speedup vs baseline: 7.8771x; 1.0148x over previous
#include <cuda_runtime.h>
#include <cuda_fp16.h>
#include <cstdint>

#define BB 8
#define CC 512
#define LL 2048

// ---------------------------------------------------------------------------
// Device scratch (all fp16 operands)
// ---------------------------------------------------------------------------
__device__ __half g_xt16[(size_t)BB * LL * CC];    // x^T [b][l][c]
__device__ __half g_w16[3 * CC * CC];              // W   [w][c_out][c_in]
__device__ __half g_qt16[(size_t)BB * LL * CC];    // q^T [b][l][c]
__device__ __half g_kt16[(size_t)BB * LL * CC];    // k^T [b][m][c]
__device__ __half g_v16[(size_t)BB * CC * LL];     // v   [b][c][m]
__device__ __half g_e16[(size_t)BB * LL * LL];     // e^s [b][l][m]
__device__ float  g_psum[(size_t)BB * LL * 16];    // partial row sums
__device__ float  g_rinv[(size_t)BB * LL];         // 1 / row sum

// ---------------------------------------------------------------------------
// Helpers (baseline PTX only)
// ---------------------------------------------------------------------------
__device__ __forceinline__ uint32_t smem_u32(const void* p) {
    uint32_t a;
    asm("{ .reg .u64 t; cvta.to.shared.u64 t, %1; cvt.u32.u64 %0, t; }"
        : "=r"(a) : "l"(p));
    return a;
}

__device__ __forceinline__ void ldsm4(uint32_t* r, uint32_t addr) {
    asm volatile("ldmatrix.sync.aligned.m8n8.x4.shared.b16 {%0,%1,%2,%3}, [%4];"
                 : "=r"(r[0]), "=r"(r[1]), "=r"(r[2]), "=r"(r[3]) : "r"(addr));
}

__device__ __forceinline__ void mma16816h(float* c, const uint32_t* a, const uint32_t* b) {
    asm volatile(
        "mma.sync.aligned.m16n8k16.row.col.f32.f16.f16.f32 "
        "{%0,%1,%2,%3}, {%4,%5,%6,%7}, {%8,%9}, {%0,%1,%2,%3};"
        : "+f"(c[0]), "+f"(c[1]), "+f"(c[2]), "+f"(c[3])
        : "r"(a[0]), "r"(a[1]), "r"(a[2]), "r"(a[3]), "r"(b[0]), "r"(b[1]));
}

#define CP16(dst, src) \
    asm volatile("cp.async.cg.shared.global [%0], [%1], 16;" :: "r"(dst), "l"(src))
#define CP_COMMIT() asm volatile("cp.async.commit_group;" ::: "memory")
#define CP_WAIT1()  asm volatile("cp.async.wait_group 1;" ::: "memory")

// ---------------------------------------------------------------------------
// Conversion kernels
// ---------------------------------------------------------------------------
__global__ __launch_bounds__(256) void conv_w(
    const float* __restrict__ Wq, const float* __restrict__ Wk,
    const float* __restrict__ Wv)
{
    int idx = blockIdx.x * 256 + threadIdx.x;
    int wsel = idx >> 18;
    int off = idx & 262143;
    const float* W = (wsel == 0) ? Wq : (wsel == 1) ? Wk : Wv;
    g_w16[idx] = __float2half(W[off]);
}

__global__ __launch_bounds__(256) void conv_x(const float* __restrict__ x)
{
    __shared__ float ts[32][33];
    int b = blockIdx.z, c0 = blockIdx.y * 32, l0 = blockIdx.x * 32;
    int lane = threadIdx.x & 31, wrp = threadIdx.x >> 5;
    const float* X = x + ((size_t)b * CC + c0) * LL + l0;
    #pragma unroll
    for (int ii = 0; ii < 4; ii++)
        ts[wrp + 8 * ii][lane] = X[(size_t)(wrp + 8 * ii) * LL + lane];
    __syncthreads();
    size_t base = ((size_t)b * LL + l0) * CC + c0;
    #pragma unroll
    for (int ii = 0; ii < 4; ii++) {
        int lr = wrp + 8 * ii;
        g_xt16[base + (size_t)lr * CC + lane] = __float2half(ts[lane][lr]);
    }
}

// ---------------------------------------------------------------------------
// Common tile copier (128 threads): 128 rows x 32 fp16 (64B), 80B pitch
// ---------------------------------------------------------------------------
__device__ __forceinline__ void cp_tile(uint32_t dst_base,
    const __half* __restrict__ g, int row0, int ld, int k0, int tid)
{
    #pragma unroll
    for (int i = 0; i < 4; i++) {
        int idx = i * 128 + tid;
        int r = idx >> 2, u = idx & 3;
        uint32_t dst = dst_base + (uint32_t)r * 80u + (uint32_t)u * 16u;
        const __half* src = g + (size_t)(row0 + r) * ld + k0 + u * 8;
        CP16(dst, src);
    }
}

// 64x64 warp tile: 4 m-subtiles x 8 n-subtiles, acc[128]
__device__ __forceinline__ void mma_block_h(float* acc, const uint32_t* af, const uint32_t* bf)
{
    #pragma unroll
    for (int i = 0; i < 4; i++)
        #pragma unroll
        for (int j = 0; j < 8; j++)
            mma16816h(acc + (i * 8 + j) * 4, af + i * 4, bf + (j >> 1) * 4 + (j & 1) * 2);
}

// ---------------------------------------------------------------------------
// Shared GEMM mainloop: CTA 128x128, 4 warps of 64x64, BK=32, 3-stage
// cp.async pipeline + register fragment double-buffering.
// Stage: A@0, B@10240; stage stride 20480; smem total 61440.
// ---------------------------------------------------------------------------
#define SMEM_DYN 61440
#define STG 20480

__device__ __forceinline__ void ld_frags(uint32_t base, uint32_t aoff, uint32_t boff,
                                         uint32_t kb, uint32_t* af, uint32_t* bf)
{
    #pragma unroll
    for (int i = 0; i < 4; i++)  ldsm4(af + i * 4, base + aoff + i * 1280 + kb);
    #pragma unroll
    for (int jp = 0; jp < 4; jp++) ldsm4(bf + jp * 4, base + 10240 + boff + jp * 1280 + kb);
}

__device__ __forceinline__ void gemm_mainloop(
    uint32_t sb, const __half* A, const __half* B, int m0, int n0,
    int lda, int ldb, int NT, int tid, uint32_t aoff, uint32_t boff, float* acc)
{
    cp_tile(sb + 0,     A, m0, lda, 0, tid);
    cp_tile(sb + 10240, B, n0, ldb, 0, tid);
    CP_COMMIT();
    if (NT > 1) {
        cp_tile(sb + STG,         A, m0, lda, 32, tid);
        cp_tile(sb + STG + 10240, B, n0, ldb, 32, tid);
    }
    CP_COMMIT();
    CP_WAIT1();
    __syncthreads();

    uint32_t af[2][16], bf[2][16];
    ld_frags(sb, aoff, boff, 0, af[0], bf[0]);

    for (int t = 0; t < NT; t++) {
        const uint32_t base = sb + (uint32_t)(t % 3) * STG;
        if (t + 2 < NT) {
            uint32_t nb = sb + (uint32_t)((t + 2) % 3) * STG;
            int k0 = (t + 2) * 32;
            cp_tile(nb + 0,     A, m0, lda, k0, tid);
            cp_tile(nb + 10240, B, n0, ldb, k0, tid);
        }
        CP_COMMIT();

        // phase ks=0: prefetch ks=1 frags, MMA on ks=0
        ld_frags(base, aoff, boff, 32, af[1], bf[1]);
        mma_block_h(acc, af[0], bf[0]);

        // phase ks=1: wait next stage, prefetch next tile's ks=0, MMA ks=1
        if (t + 1 < NT) {
            CP_WAIT1();
            __syncthreads();
            const uint32_t nbase = sb + (uint32_t)((t + 1) % 3) * STG;
            ld_frags(nbase, aoff, boff, 0, af[0], bf[0]);
        }
        mma_block_h(acc, af[1], bf[1]);
    }
}

#define WARP_GEOM \
    const int tid = threadIdx.x; \
    const int lane = tid & 31, wid = tid >> 5; \
    const int wm = wid & 1, wn = wid >> 1; \
    const uint32_t aoff = (uint32_t)((wm * 64 + (lane & 15)) * 80 + ((lane >> 4) * 16)); \
    const uint32_t boff = (uint32_t)((wn * 64 + (((lane >> 3) >> 1) * 8) + (lane & 7)) * 80 \
                                     + ((lane >> 3) & 1) * 16);

// ---------------------------------------------------------------------------
// proj: fp16 GEMM. wsel<2: D[l][c_out]=x_t*W^T -> q/k ; wsel=2: D[c][l] -> v
// ---------------------------------------------------------------------------
__global__ __launch_bounds__(128, 2) void proj_kernel(
    const float* __restrict__ bq, const float* __restrict__ bk,
    const float* __restrict__ bv)
{
    extern __shared__ char smem[];
    const uint32_t sb = smem_u32(smem);
    WARP_GEOM

    int id = blockIdx.x;
    int b = blockIdx.y / 3, wsel = blockIdx.y % 3;
    const __half *A, *B;
    int m0, n0;
    if (wsel < 2) {
        m0 = (id >> 2) * 128; n0 = (id & 3) * 128;           // m=l, n=c_out
        A = g_xt16 + (size_t)b * LL * CC;
        B = g_w16 + (size_t)wsel * CC * CC;
    } else {
        m0 = (id & 3) * 128; n0 = (id >> 2) * 128;           // m=c_out, n=l
        A = g_w16 + (size_t)2 * CC * CC;
        B = g_xt16 + (size_t)b * LL * CC;
    }

    float acc[128];
    #pragma unroll
    for (int i = 0; i < 128; i++) acc[i] = 0.f;

    gemm_mainloop(sb, A, B, m0, n0, CC, CC, CC / 32, tid, aoff, boff, acc);

    const int mb = m0 + wm * 64;
    const int nb = n0 + wn * 64;

    if (wsel < 2) {
        const float* bias = (wsel == 0) ? bq : bk;
        __half* Q = ((wsel == 0) ? g_qt16 : g_kt16) + (size_t)b * LL * CC;
        #pragma unroll
        for (int i = 0; i < 4; i++) {
            int r0 = mb + i * 16 + (lane >> 2);
            #pragma unroll
            for (int j = 0; j < 8; j++) {
                const float* c = acc + (i * 8 + j) * 4;
                int nn = nb + j * 8 + (lane & 3) * 2;
                float b0 = bias[nn], b1 = bias[nn + 1];
                *(__half2*)(Q + (size_t)r0 * CC + nn) =
                    __floats2half2_rn(c[0] + b0, c[1] + b1);
                *(__half2*)(Q + (size_t)(r0 + 8) * CC + nn) =
                    __floats2half2_rn(c[2] + b0, c[3] + b1);
            }
        }
    } else {
        __half* V = g_v16 + (size_t)b * CC * LL;
        #pragma unroll
        for (int i = 0; i < 4; i++) {
            int r0 = mb + i * 16 + (lane >> 2);
            float bi0 = bv[r0], bi8 = bv[r0 + 8];
            #pragma unroll
            for (int j = 0; j < 8; j++) {
                const float* c = acc + (i * 8 + j) * 4;
                int nn = nb + j * 8 + (lane & 3) * 2;
                *(__half2*)(V + (size_t)r0 * LL + nn) =
                    __floats2half2_rn(c[0] + bi0, c[1] + bi0);
                *(__half2*)(V + (size_t)(r0 + 8) * LL + nn) =
                    __floats2half2_rn(c[2] + bi8, c[3] + bi8);
            }
        }
    }
}

// ---------------------------------------------------------------------------
// scores: D = q_t * k_t^T; emits e^(s*scale) fp16 + row partial sums
// ---------------------------------------------------------------------------
__global__ __launch_bounds__(128, 2) void scores_kernel()
{
    extern __shared__ char smem[];
    const uint32_t sb = smem_u32(smem);
    WARP_GEOM

    const int b = blockIdx.y;
    const int m0 = (blockIdx.x >> 4) * 128;    // l
    const int n0 = (blockIdx.x & 15) * 128;    // m
    const __half* Q = g_qt16 + (size_t)b * LL * CC;
    const __half* K = g_kt16 + (size_t)b * LL * CC;

    float acc[128];
    #pragma unroll
    for (int i = 0; i < 128; i++) acc[i] = 0.f;

    gemm_mainloop(sb, Q, K, m0, n0, CC, CC, CC / 32, tid, aoff, boff, acc);

    const float scale = 0.044194173824159216f;   // 1/sqrt(512)
    const int mb = m0 + wm * 64;
    const int nb = n0 + wn * 64;
    __half* E = g_e16 + (size_t)b * LL * LL;

    __syncthreads();
    float* ps = (float*)smem;                     // [128][2]

    #pragma unroll
    for (int i = 0; i < 4; i++) {
        int r0 = mb + i * 16 + (lane >> 2);
        float sA = 0.f, sB = 0.f;
        #pragma unroll
        for (int j = 0; j < 8; j++) {
            const float* c = acc + (i * 8 + j) * 4;
            int nn = nb + j * 8 + (lane & 3) * 2;
            float e0 = __expf(fminf(c[0] * scale, 11.f));
            float e1 = __expf(fminf(c[1] * scale, 11.f));
            float e2 = __expf(fminf(c[2] * scale, 11.f));
            float e3 = __expf(fminf(c[3] * scale, 11.f));
            *(__half2*)(E + (size_t)r0 * LL + nn)       = __floats2half2_rn(e0, e1);
            *(__half2*)(E + (size_t)(r0 + 8) * LL + nn) = __floats2half2_rn(e2, e3);
            sA += e0 + e1;
            sB += e2 + e3;
        }
        #pragma unroll
        for (int o = 1; o <= 2; o <<= 1) {
            sA += __shfl_xor_sync(0xFFFFFFFFu, sA, o);
            sB += __shfl_xor_sync(0xFFFFFFFFu, sB, o);
        }
        if ((lane & 3) == 0) {
            int rloc = wm * 64 + i * 16 + (lane >> 2);
            ps[rloc * 2 + wn]       = sA;
            ps[(rloc + 8) * 2 + wn] = sB;
        }
    }
    __syncthreads();
    {
        float s = ps[tid * 2] + ps[tid * 2 + 1];
        g_psum[((size_t)b * LL + m0 + tid) * 16 + (n0 >> 7)] = s;
    }
}

// ---------------------------------------------------------------------------
// rowinv: 1 / sum of 16 partials per (b, l)
// ---------------------------------------------------------------------------
__global__ __launch_bounds__(256) void rowinv_kernel()
{
    int i = blockIdx.x * 256 + threadIdx.x;
    const float* p = &g_psum[(size_t)i * 16];
    float s = 0.f;
    #pragma unroll
    for (int k = 0; k < 16; k++) s += p[k];
    g_rinv[i] = 1.f / s;
}

// ---------------------------------------------------------------------------
// out = (V * E^T) * rinv
// ---------------------------------------------------------------------------
__global__ __launch_bounds__(128, 2) void out_kernel(float* __restrict__ outp)
{
    extern __shared__ char smem[];
    const uint32_t sb = smem_u32(smem);
    WARP_GEOM

    const int b = blockIdx.y;
    const int m0 = (blockIdx.x & 3) * 128;     // c
    const int n0 = (blockIdx.x >> 2) * 128;    // l
    const __half* V = g_v16 + (size_t)b * CC * LL;
    const __half* E = g_e16 + (size_t)b * LL * LL;

    float acc[128];
    #pragma unroll
    for (int i = 0; i < 128; i++) acc[i] = 0.f;

    gemm_mainloop(sb, V, E, m0, n0, LL, LL, LL / 32, tid, aoff, boff, acc);

    const int mb = m0 + wm * 64;
    const int nb = n0 + wn * 64;
    const float* Rinv = g_rinv + (size_t)b * LL;
    float rv[16];
    #pragma unroll
    for (int j = 0; j < 8; j++) {
        int nn = nb + j * 8 + (lane & 3) * 2;
        float2 r2 = *(const float2*)&Rinv[nn];
        rv[j * 2] = r2.x; rv[j * 2 + 1] = r2.y;
    }

    float* O = outp + (size_t)b * CC * LL;
    #pragma unroll
    for (int i = 0; i < 4; i++) {
        int r0 = mb + i * 16 + (lane >> 2);
        #pragma unroll
        for (int j = 0; j < 8; j++) {
            const float* c = acc + (i * 8 + j) * 4;
            int nn = nb + j * 8 + (lane & 3) * 2;
            float2 v0 = {c[0] * rv[j * 2], c[1] * rv[j * 2 + 1]};
            float2 v1 = {c[2] * rv[j * 2], c[3] * rv[j * 2 + 1]};
            *(float2*)&O[(size_t)r0 * LL + nn]       = v0;
            *(float2*)&O[(size_t)(r0 + 8) * LL + nn] = v1;
        }
    }
}

// ---------------------------------------------------------------------------
extern "C" void kernel_launch(void* const* d_in, const int* in_sizes, int n_in,
                              void* d_out, int out_size)
{
    const float* x  = (const float*)d_in[0];
    const float* Wq = (const float*)d_in[1];
    const float* bq = (const float*)d_in[2];
    const float* Wk = (const float*)d_in[3];
    const float* bk = (const float*)d_in[4];
    const float* Wv = (const float*)d_in[5];
    const float* bv = (const float*)d_in[6];
    float* out = (float*)d_out;

    cudaFuncSetAttribute(proj_kernel,   cudaFuncAttributeMaxDynamicSharedMemorySize, SMEM_DYN);
    cudaFuncSetAttribute(scores_kernel, cudaFuncAttributeMaxDynamicSharedMemorySize, SMEM_DYN);
    cudaFuncSetAttribute(out_kernel,    cudaFuncAttributeMaxDynamicSharedMemorySize, SMEM_DYN);

    conv_w<<<3 * CC * CC / 256, 256>>>(Wq, Wk, Wv);
    conv_x<<<dim3(LL / 32, CC / 32, BB), 256>>>(x);

    proj_kernel<<<dim3(64, 3 * BB), 128, SMEM_DYN>>>(bq, bk, bv);
    scores_kernel<<<dim3(256, BB), 128, SMEM_DYN>>>();
    rowinv_kernel<<<BB * LL / 256, 256>>>();
    out_kernel<<<dim3(64, BB), 128, SMEM_DYN>>>(out);
}

// round 10
// speedup vs baseline: 8.0170x; 1.0178x over previous
#include <cuda_runtime.h>
#include <cuda_fp16.h>
#include <cstdint>

#define BB 8
#define CC 512
#define LL 2048

// ---------------------------------------------------------------------------
// Device scratch (all fp16 operands)
// ---------------------------------------------------------------------------
__device__ __half g_xt16[(size_t)BB * LL * CC];    // x^T [b][l][c]
__device__ __half g_w16[3 * CC * CC];              // W   [w][c_out][c_in]
__device__ __half g_qt16[(size_t)BB * LL * CC];    // q^T [b][l][c]
__device__ __half g_kt16[(size_t)BB * LL * CC];    // k^T [b][m][c]
__device__ __half g_v16[(size_t)BB * CC * LL];     // v   [b][c][m]
__device__ __half g_e16[(size_t)BB * LL * LL];     // e^s [b][l][m]
__device__ float  g_psum[(size_t)BB * LL * 16];    // partial row sums

// ---------------------------------------------------------------------------
// Helpers (baseline PTX only)
// ---------------------------------------------------------------------------
__device__ __forceinline__ uint32_t smem_u32(const void* p) {
    uint32_t a;
    asm("{ .reg .u64 t; cvta.to.shared.u64 t, %1; cvt.u32.u64 %0, t; }"
        : "=r"(a) : "l"(p));
    return a;
}

__device__ __forceinline__ void ldsm4(uint32_t* r, uint32_t addr) {
    asm volatile("ldmatrix.sync.aligned.m8n8.x4.shared.b16 {%0,%1,%2,%3}, [%4];"
                 : "=r"(r[0]), "=r"(r[1]), "=r"(r[2]), "=r"(r[3]) : "r"(addr));
}

__device__ __forceinline__ void mma16816h(float* c, const uint32_t* a, const uint32_t* b) {
    asm volatile(
        "mma.sync.aligned.m16n8k16.row.col.f32.f16.f16.f32 "
        "{%0,%1,%2,%3}, {%4,%5,%6,%7}, {%8,%9}, {%0,%1,%2,%3};"
        : "+f"(c[0]), "+f"(c[1]), "+f"(c[2]), "+f"(c[3])
        : "r"(a[0]), "r"(a[1]), "r"(a[2]), "r"(a[3]), "r"(b[0]), "r"(b[1]));
}

#define CP16(dst, src) \
    asm volatile("cp.async.cg.shared.global [%0], [%1], 16;" :: "r"(dst), "l"(src))
#define CP_COMMIT() asm volatile("cp.async.commit_group;" ::: "memory")
#define CP_WAIT1()  asm volatile("cp.async.wait_group 1;" ::: "memory")

// ---------------------------------------------------------------------------
// Fused conversion kernel: z<BB -> x transpose+convert for batch z;
// z==BB -> W convert (each thread does one element of Wq, Wk, Wv).
// ---------------------------------------------------------------------------
__global__ __launch_bounds__(256) void conv_fused(
    const float* __restrict__ x,
    const float* __restrict__ Wq, const float* __restrict__ Wk,
    const float* __restrict__ Wv)
{
    int z = blockIdx.z;
    if (z < BB) {
        __shared__ float ts[32][33];
        int b = z, c0 = blockIdx.y * 32, l0 = blockIdx.x * 32;
        int lane = threadIdx.x & 31, wrp = threadIdx.x >> 5;
        const float* X = x + ((size_t)b * CC + c0) * LL + l0;
        #pragma unroll
        for (int ii = 0; ii < 4; ii++)
            ts[wrp + 8 * ii][lane] = X[(size_t)(wrp + 8 * ii) * LL + lane];
        __syncthreads();
        size_t base = ((size_t)b * LL + l0) * CC + c0;
        #pragma unroll
        for (int ii = 0; ii < 4; ii++) {
            int lr = wrp + 8 * ii;
            g_xt16[base + (size_t)lr * CC + lane] = __float2half(ts[lane][lr]);
        }
    } else {
        // 1024 blocks x 256 threads = 262144 = CC*CC threads
        int t = (blockIdx.y * 64 + blockIdx.x) * 256 + threadIdx.x;
        g_w16[t]          = __float2half(Wq[t]);
        g_w16[t + 262144] = __float2half(Wk[t]);
        g_w16[t + 524288] = __float2half(Wv[t]);
    }
}

// ---------------------------------------------------------------------------
// Common tile copier (128 threads): 128 rows x 32 fp16 (64B), 80B pitch
// ---------------------------------------------------------------------------
__device__ __forceinline__ void cp_tile(uint32_t dst_base,
    const __half* __restrict__ g, int row0, int ld, int k0, int tid)
{
    #pragma unroll
    for (int i = 0; i < 4; i++) {
        int idx = i * 128 + tid;
        int r = idx >> 2, u = idx & 3;
        uint32_t dst = dst_base + (uint32_t)r * 80u + (uint32_t)u * 16u;
        const __half* src = g + (size_t)(row0 + r) * ld + k0 + u * 8;
        CP16(dst, src);
    }
}

// 64x64 warp tile: 4 m-subtiles x 8 n-subtiles, acc[128]
__device__ __forceinline__ void mma_block_h(float* acc, const uint32_t* af, const uint32_t* bf)
{
    #pragma unroll
    for (int i = 0; i < 4; i++)
        #pragma unroll
        for (int j = 0; j < 8; j++)
            mma16816h(acc + (i * 8 + j) * 4, af + i * 4, bf + (j >> 1) * 4 + (j & 1) * 2);
}

// ---------------------------------------------------------------------------
// Shared GEMM mainloop: CTA 128x128, 4 warps of 64x64, BK=32, 3-stage
// cp.async pipeline + register fragment double-buffering.
// Stage: A@0, B@10240; stage stride 20480; stages total 61440.
// ---------------------------------------------------------------------------
#define STAGE_BYTES 61440
#define SMEM_DYN  (STAGE_BYTES + 512)    // + rinv[128] for out_kernel
#define STG 20480

__device__ __forceinline__ void ld_frags(uint32_t base, uint32_t aoff, uint32_t boff,
                                         uint32_t kb, uint32_t* af, uint32_t* bf)
{
    #pragma unroll
    for (int i = 0; i < 4; i++)  ldsm4(af + i * 4, base + aoff + i * 1280 + kb);
    #pragma unroll
    for (int jp = 0; jp < 4; jp++) ldsm4(bf + jp * 4, base + 10240 + boff + jp * 1280 + kb);
}

__device__ __forceinline__ void gemm_mainloop(
    uint32_t sb, const __half* A, const __half* B, int m0, int n0,
    int lda, int ldb, int NT, int tid, uint32_t aoff, uint32_t boff, float* acc)
{
    CP_WAIT1();
    __syncthreads();

    uint32_t af[2][16], bf[2][16];
    ld_frags(sb, aoff, boff, 0, af[0], bf[0]);

    for (int t = 0; t < NT; t++) {
        const uint32_t base = sb + (uint32_t)(t % 3) * STG;
        if (t + 2 < NT) {
            uint32_t nb = sb + (uint32_t)((t + 2) % 3) * STG;
            int k0 = (t + 2) * 32;
            cp_tile(nb + 0,     A, m0, lda, k0, tid);
            cp_tile(nb + 10240, B, n0, ldb, k0, tid);
        }
        CP_COMMIT();

        // phase ks=0: prefetch ks=1 frags, MMA on ks=0
        ld_frags(base, aoff, boff, 32, af[1], bf[1]);
        mma_block_h(acc, af[0], bf[0]);

        // phase ks=1: wait next stage, prefetch next tile's ks=0, MMA ks=1
        if (t + 1 < NT) {
            CP_WAIT1();
            __syncthreads();
            const uint32_t nbase = sb + (uint32_t)((t + 1) % 3) * STG;
            ld_frags(nbase, aoff, boff, 0, af[0], bf[0]);
        }
        mma_block_h(acc, af[1], bf[1]);
    }
}

__device__ __forceinline__ void gemm_prologue(
    uint32_t sb, const __half* A, const __half* B, int m0, int n0,
    int lda, int ldb, int NT, int tid)
{
    cp_tile(sb + 0,     A, m0, lda, 0, tid);
    cp_tile(sb + 10240, B, n0, ldb, 0, tid);
    CP_COMMIT();
    if (NT > 1) {
        cp_tile(sb + STG,         A, m0, lda, 32, tid);
        cp_tile(sb + STG + 10240, B, n0, ldb, 32, tid);
    }
    CP_COMMIT();
}

#define WARP_GEOM \
    const int tid = threadIdx.x; \
    const int lane = tid & 31, wid = tid >> 5; \
    const int wm = wid & 1, wn = wid >> 1; \
    const uint32_t aoff = (uint32_t)((wm * 64 + (lane & 15)) * 80 + ((lane >> 4) * 16)); \
    const uint32_t boff = (uint32_t)((wn * 64 + (((lane >> 3) >> 1) * 8) + (lane & 7)) * 80 \
                                     + ((lane >> 3) & 1) * 16);

// ---------------------------------------------------------------------------
// proj: fp16 GEMM. wsel<2: D[l][c_out]=x_t*W^T -> q/k ; wsel=2: D[c][l] -> v
// ---------------------------------------------------------------------------
__global__ __launch_bounds__(128, 2) void proj_kernel(
    const float* __restrict__ bq, const float* __restrict__ bk,
    const float* __restrict__ bv)
{
    extern __shared__ char smem[];
    const uint32_t sb = smem_u32(smem);
    WARP_GEOM

    int id = blockIdx.x;
    int b = blockIdx.y / 3, wsel = blockIdx.y % 3;
    const __half *A, *B;
    int m0, n0;
    if (wsel < 2) {
        m0 = (id >> 2) * 128; n0 = (id & 3) * 128;           // m=l, n=c_out
        A = g_xt16 + (size_t)b * LL * CC;
        B = g_w16 + (size_t)wsel * CC * CC;
    } else {
        m0 = (id & 3) * 128; n0 = (id >> 2) * 128;           // m=c_out, n=l
        A = g_w16 + (size_t)2 * CC * CC;
        B = g_xt16 + (size_t)b * LL * CC;
    }

    float acc[128];
    #pragma unroll
    for (int i = 0; i < 128; i++) acc[i] = 0.f;

    gemm_prologue(sb, A, B, m0, n0, CC, CC, CC / 32, tid);
    gemm_mainloop(sb, A, B, m0, n0, CC, CC, CC / 32, tid, aoff, boff, acc);

    const int mb = m0 + wm * 64;
    const int nb = n0 + wn * 64;

    if (wsel < 2) {
        const float* bias = (wsel == 0) ? bq : bk;
        __half* Q = ((wsel == 0) ? g_qt16 : g_kt16) + (size_t)b * LL * CC;
        #pragma unroll
        for (int i = 0; i < 4; i++) {
            int r0 = mb + i * 16 + (lane >> 2);
            #pragma unroll
            for (int j = 0; j < 8; j++) {
                const float* c = acc + (i * 8 + j) * 4;
                int nn = nb + j * 8 + (lane & 3) * 2;
                float b0 = bias[nn], b1 = bias[nn + 1];
                *(__half2*)(Q + (size_t)r0 * CC + nn) =
                    __floats2half2_rn(c[0] + b0, c[1] + b1);
                *(__half2*)(Q + (size_t)(r0 + 8) * CC + nn) =
                    __floats2half2_rn(c[2] + b0, c[3] + b1);
            }
        }
    } else {
        __half* V = g_v16 + (size_t)b * CC * LL;
        #pragma unroll
        for (int i = 0; i < 4; i++) {
            int r0 = mb + i * 16 + (lane >> 2);
            float bi0 = bv[r0], bi8 = bv[r0 + 8];
            #pragma unroll
            for (int j = 0; j < 8; j++) {
                const float* c = acc + (i * 8 + j) * 4;
                int nn = nb + j * 8 + (lane & 3) * 2;
                *(__half2*)(V + (size_t)r0 * LL + nn) =
                    __floats2half2_rn(c[0] + bi0, c[1] + bi0);
                *(__half2*)(V + (size_t)(r0 + 8) * LL + nn) =
                    __floats2half2_rn(c[2] + bi8, c[3] + bi8);
            }
        }
    }
}

// ---------------------------------------------------------------------------
// scores: D = q_t * k_t^T; emits e^(s*scale) fp16 + row partial sums
// ---------------------------------------------------------------------------
__global__ __launch_bounds__(128, 2) void scores_kernel()
{
    extern __shared__ char smem[];
    const uint32_t sb = smem_u32(smem);
    WARP_GEOM

    const int b = blockIdx.y;
    const int m0 = (blockIdx.x >> 4) * 128;    // l
    const int n0 = (blockIdx.x & 15) * 128;    // m
    const __half* Q = g_qt16 + (size_t)b * LL * CC;
    const __half* K = g_kt16 + (size_t)b * LL * CC;

    float acc[128];
    #pragma unroll
    for (int i = 0; i < 128; i++) acc[i] = 0.f;

    gemm_prologue(sb, Q, K, m0, n0, CC, CC, CC / 32, tid);
    gemm_mainloop(sb, Q, K, m0, n0, CC, CC, CC / 32, tid, aoff, boff, acc);

    const float scale = 0.044194173824159216f;   // 1/sqrt(512)
    const int mb = m0 + wm * 64;
    const int nb = n0 + wn * 64;
    __half* E = g_e16 + (size_t)b * LL * LL;

    __syncthreads();
    float* ps = (float*)smem;                     // [128][2]

    #pragma unroll
    for (int i = 0; i < 4; i++) {
        int r0 = mb + i * 16 + (lane >> 2);
        float sA = 0.f, sB = 0.f;
        #pragma unroll
        for (int j = 0; j < 8; j++) {
            const float* c = acc + (i * 8 + j) * 4;
            int nn = nb + j * 8 + (lane & 3) * 2;
            float e0 = __expf(fminf(c[0] * scale, 11.f));
            float e1 = __expf(fminf(c[1] * scale, 11.f));
            float e2 = __expf(fminf(c[2] * scale, 11.f));
            float e3 = __expf(fminf(c[3] * scale, 11.f));
            *(__half2*)(E + (size_t)r0 * LL + nn)       = __floats2half2_rn(e0, e1);
            *(__half2*)(E + (size_t)(r0 + 8) * LL + nn) = __floats2half2_rn(e2, e3);
            sA += e0 + e1;
            sB += e2 + e3;
        }
        #pragma unroll
        for (int o = 1; o <= 2; o <<= 1) {
            sA += __shfl_xor_sync(0xFFFFFFFFu, sA, o);
            sB += __shfl_xor_sync(0xFFFFFFFFu, sB, o);
        }
        if ((lane & 3) == 0) {
            int rloc = wm * 64 + i * 16 + (lane >> 2);
            ps[rloc * 2 + wn]       = sA;
            ps[(rloc + 8) * 2 + wn] = sB;
        }
    }
    __syncthreads();
    {
        float s = ps[tid * 2] + ps[tid * 2 + 1];
        g_psum[((size_t)b * LL + m0 + tid) * 16 + (n0 >> 7)] = s;
    }
}

// ---------------------------------------------------------------------------
// out = (V * E^T) * rinv.  rinv computed in-CTA from g_psum (no extra kernel).
// ---------------------------------------------------------------------------
__global__ __launch_bounds__(128, 2) void out_kernel(float* __restrict__ outp)
{
    extern __shared__ char smem[];
    const uint32_t sb = smem_u32(smem);
    WARP_GEOM

    const int b = blockIdx.y;
    const int m0 = (blockIdx.x & 3) * 128;     // c
    const int n0 = (blockIdx.x >> 2) * 128;    // l
    const __half* V = g_v16 + (size_t)b * CC * LL;
    const __half* E = g_e16 + (size_t)b * LL * LL;

    float acc[128];
    #pragma unroll
    for (int i = 0; i < 128; i++) acc[i] = 0.f;

    gemm_prologue(sb, V, E, m0, n0, LL, LL, LL / 32, tid);

    // rinv for this CTA's 128 l-rows, overlapped with the cp.async prologue.
    // Visible to all threads by the mainloop's internal barriers (NT >= 2).
    float* srinv = (float*)(smem + STAGE_BYTES);
    {
        const float* p = &g_psum[((size_t)b * LL + n0 + tid) * 16];
        float s = 0.f;
        #pragma unroll
        for (int k = 0; k < 16; k++) s += p[k];
        srinv[tid] = 1.f / s;
    }

    gemm_mainloop(sb, V, E, m0, n0, LL, LL, LL / 32, tid, aoff, boff, acc);

    const int mb = m0 + wm * 64;
    const int nb = n0 + wn * 64;
    float rv[16];
    #pragma unroll
    for (int j = 0; j < 8; j++) {
        int nn = (nb - n0) + j * 8 + (lane & 3) * 2;
        float2 r2 = *(const float2*)&srinv[nn];
        rv[j * 2] = r2.x; rv[j * 2 + 1] = r2.y;
    }

    float* O = outp + (size_t)b * CC * LL;
    #pragma unroll
    for (int i = 0; i < 4; i++) {
        int r0 = mb + i * 16 + (lane >> 2);
        #pragma unroll
        for (int j = 0; j < 8; j++) {
            const float* c = acc + (i * 8 + j) * 4;
            int nn = nb + j * 8 + (lane & 3) * 2;
            float2 v0 = {c[0] * rv[j * 2], c[1] * rv[j * 2 + 1]};
            float2 v1 = {c[2] * rv[j * 2], c[3] * rv[j * 2 + 1]};
            *(float2*)&O[(size_t)r0 * LL + nn]       = v0;
            *(float2*)&O[(size_t)(r0 + 8) * LL + nn] = v1;
        }
    }
}

// ---------------------------------------------------------------------------
extern "C" void kernel_launch(void* const* d_in, const int* in_sizes, int n_in,
                              void* d_out, int out_size)
{
    const float* x  = (const float*)d_in[0];
    const float* Wq = (const float*)d_in[1];
    const float* bq = (const float*)d_in[2];
    const float* Wk = (const float*)d_in[3];
    const float* bk = (const float*)d_in[4];
    const float* Wv = (const float*)d_in[5];
    const float* bv = (const float*)d_in[6];
    float* out = (float*)d_out;

    cudaFuncSetAttribute(proj_kernel,   cudaFuncAttributeMaxDynamicSharedMemorySize, SMEM_DYN);
    cudaFuncSetAttribute(scores_kernel, cudaFuncAttributeMaxDynamicSharedMemorySize, SMEM_DYN);
    cudaFuncSetAttribute(out_kernel,    cudaFuncAttributeMaxDynamicSharedMemorySize, SMEM_DYN);

    conv_fused<<<dim3(LL / 32, CC / 32, BB + 1), 256>>>(x, Wq, Wk, Wv);

    proj_kernel<<<dim3(64, 3 * BB), 128, SMEM_DYN>>>(bq, bk, bv);
    scores_kernel<<<dim3(256, BB), 128, SMEM_DYN>>>();
    out_kernel<<<dim3(64, BB), 128, SMEM_DYN>>>(out);
}